// round 8
// baseline (speedup 1.0000x reference)
#include <cuda_runtime.h>
#include <cuda_bf16.h>
#include <cstdint>

#define NN   50000
#define IND  256
#define HID  128
#define OUTD 64
#define EMAX 800000

// scan config: small chunks for full-chip occupancy
#define SC_T     256
#define SC_I     2
#define SC_CHUNK (SC_T * SC_I)                     // 512
#define SC_NB    ((NN + SC_CHUNK - 1) / SC_CHUNK)  // 98

#define CHUNK    25000   // tail pipeline row chunk

// -------- device scratch --------
__device__ float g_h1[NN * HID];
__device__ float g_agg1[NN * HID];
__device__ float g_h2[NN * OUTD];
__device__ float g_dinv[NN];
__device__ int   g_deg[NN];          // raw in-edge counts (no self loop)
__device__ int   g_rowptr[NN + 1];
__device__ int   g_fill[NN];
__device__ int   g_csrc[EMAX];
__device__ int   g_bsum[SC_NB];
__device__ int   g_boff[SC_NB];
__device__ __nv_bfloat16 g_w1hi[HID * IND];
__device__ __nv_bfloat16 g_w1lo[HID * IND];
__device__ __nv_bfloat16 g_w2hi[OUTD * HID];
__device__ __nv_bfloat16 g_w2lo[OUTD * HID];

// ---------------- prep: deg=0 + both weight splits in ONE launch ----------------
__global__ void prep_kernel(int* __restrict__ deg,
                            const float* __restrict__ W1, const float* __restrict__ W2,
                            __nv_bfloat16* __restrict__ T1h, __nv_bfloat16* __restrict__ T1l,
                            __nv_bfloat16* __restrict__ T2h, __nv_bfloat16* __restrict__ T2l) {
    int i = blockIdx.x * blockDim.x + threadIdx.x;
    if (i < NN) deg[i] = 0;
    const int n1 = IND * HID;
    const int n2 = HID * OUTD;
    if (i < n1) {
        int k = i / HID, n = i % HID;
        float v = W1[i];
        __nv_bfloat16 h = __float2bfloat16(v);
        T1h[(size_t)n * IND + k] = h;
        T1l[(size_t)n * IND + k] = __float2bfloat16(v - __bfloat162float(h));
    } else if (i < n1 + n2) {
        int j = i - n1;
        int k = j / OUTD, n = j % OUTD;
        float v = W2[j];
        __nv_bfloat16 h = __float2bfloat16(v);
        T2h[(size_t)n * HID + k] = h;
        T2l[(size_t)n * HID + k] = __float2bfloat16(v - __bfloat162float(h));
    }
}

__global__ void deg_count_kernel(const int* __restrict__ dst, int* __restrict__ deg, int E) {
    int i = blockIdx.x * blockDim.x + threadIdx.x;
    if (i < E) atomicAdd(&deg[dst[i]], 1);
}

// ---------------- scan chain (98 blocks, coalesced) ----------------
// block sums of deg (counts), plus dinv = rsqrt(deg+1)
__global__ void scan_reduce_kernel(const int* __restrict__ deg, int* __restrict__ bsum,
                                   float* __restrict__ dinv, int n) {
    __shared__ int ws[SC_T / 32];
    int b = blockIdx.x, tid = threadIdx.x;
    int base = b * SC_CHUNK;
    int s = 0;
#pragma unroll
    for (int u = 0; u < SC_I; u++) {
        int i = base + u * SC_T + tid;
        if (i < n) {
            int c = deg[i];
            s += c;
            dinv[i] = rsqrtf((float)(c + 1));
        }
    }
#pragma unroll
    for (int d = 16; d; d >>= 1) s += __shfl_down_sync(0xffffffffu, s, d);
    if ((tid & 31) == 0) ws[tid >> 5] = s;
    __syncthreads();
    if (tid < 32) {
        int v = (tid < SC_T / 32) ? ws[tid] : 0;
#pragma unroll
        for (int d = 16; d; d >>= 1) v += __shfl_down_sync(0xffffffffu, v, d);
        if (tid == 0) bsum[b] = v;
    }
}

// 128-thread scan over SC_NB (=98) block sums
__global__ void scan_offsets_kernel(const int* __restrict__ bsum, int* __restrict__ boff,
                                    int* __restrict__ rowptr, int n) {
    __shared__ int ws[4];
    int tid = threadIdx.x;
    int lane = tid & 31, wid = tid >> 5;
    int v = (tid < SC_NB) ? bsum[tid] : 0;
    int x = v;
#pragma unroll
    for (int d = 1; d < 32; d <<= 1) {
        int y = __shfl_up_sync(0xffffffffu, x, d);
        if (lane >= d) x += y;
    }
    if (lane == 31) ws[wid] = x;
    __syncthreads();
    if (tid == 0) {
        int acc = 0;
#pragma unroll
        for (int k = 0; k < 4; k++) { int t = ws[k]; ws[k] = acc; acc += t; }
        rowptr[n] = acc;
    }
    __syncthreads();
    if (tid < SC_NB) boff[tid] = x - v + ws[wid];
}

// writes rowptr AND fill (atomic cursor copy)
__global__ void scan_write_kernel(const int* __restrict__ deg, const int* __restrict__ boff,
                                  int* __restrict__ rowptr, int* __restrict__ fill, int n) {
    __shared__ int sbuf[SC_CHUNK];
    __shared__ int ws[SC_T / 32];
    int b = blockIdx.x, tid = threadIdx.x;
    int lane = tid & 31, wid = tid >> 5;
    int base = b * SC_CHUNK;

#pragma unroll
    for (int u = 0; u < SC_I; u++) {
        int i = base + u * SC_T + tid;
        sbuf[u * SC_T + tid] = (i < n) ? deg[i] : 0;
    }
    __syncthreads();

    int v[SC_I];
    int tot = 0;
#pragma unroll
    for (int u = 0; u < SC_I; u++) {
        int d = sbuf[tid * SC_I + u];
        v[u] = tot;
        tot += d;
    }
    int x = tot;
#pragma unroll
    for (int d = 1; d < 32; d <<= 1) {
        int y = __shfl_up_sync(0xffffffffu, x, d);
        if (lane >= d) x += y;
    }
    if (lane == 31) ws[wid] = x;
    __syncthreads();
    if (wid == 0) {
        int y = (lane < SC_T / 32) ? ws[lane] : 0;
#pragma unroll
        for (int d = 1; d < 32; d <<= 1) {
            int z = __shfl_up_sync(0xffffffffu, y, d);
            if (lane >= d) y += z;
        }
        if (lane < SC_T / 32) ws[lane] = y;
    }
    __syncthreads();
    int off = boff[b] + (x - tot) + (wid ? ws[wid - 1] : 0);
#pragma unroll
    for (int u = 0; u < SC_I; u++) sbuf[tid * SC_I + u] = off + v[u];
    __syncthreads();

#pragma unroll
    for (int u = 0; u < SC_I; u++) {
        int i = base + u * SC_T + tid;
        if (i < n) {
            int r = sbuf[u * SC_T + tid];
            rowptr[i] = r;
            fill[i] = r;
        }
    }
}

__global__ void fill_kernel(const int* __restrict__ src, const int* __restrict__ dst,
                            int* __restrict__ fill, int* __restrict__ csrc, int E) {
    int i = blockIdx.x * blockDim.x + threadIdx.x;
    if (i >= E) return;
    int pos = atomicAdd(&fill[dst[i]], 1);
    csrc[pos] = src[i];
}

// ---------------- split-bf16 tensor-core GEMM ----------------
#define MMA_BF16(c, a, b) asm volatile( \
    "mma.sync.aligned.m16n8k16.row.col.f32.bf16.bf16.f32 " \
    "{%0,%1,%2,%3}, {%4,%5,%6,%7}, {%8,%9}, {%0,%1,%2,%3};" \
    : "+f"((c)[0]), "+f"((c)[1]), "+f"((c)[2]), "+f"((c)[3]) \
    : "r"((a)[0]), "r"((a)[1]), "r"((a)[2]), "r"((a)[3]), "r"((b)[0]), "r"((b)[1]))

template<int BN, int WGM, int WGN, bool FUSE>
__global__ __launch_bounds__(256)
void mma_gemm_kernel(const float* __restrict__ A,
                     const __nv_bfloat16* __restrict__ BThi,
                     const __nv_bfloat16* __restrict__ BTlo,
                     const float* __restrict__ bias,
                     const float* __restrict__ rowscale,
                     float* __restrict__ C, int M, int K) {
    constexpr int BM = 128, BK = 16, BKP = 20;
    constexpr int MI = BM / (WGM * 16);
    constexpr int NI = BN / (WGN * 8);
    constexpr int NBU = BN * 8 / 256;

    __shared__ __nv_bfloat16 sAhi[2][BM][BKP], sAlo[2][BM][BKP];
    __shared__ __nv_bfloat16 sBhi[2][BN][BKP], sBlo[2][BN][BKP];

    const int tid  = threadIdx.x;
    const int m0   = blockIdx.x * BM;
    const int w    = tid >> 5, lane = tid & 31;
    const int wm   = (w / WGN) * MI * 16;
    const int wn   = (w % WGN) * NI * 8;
    const int gid  = lane >> 2, tig = lane & 3;

    float4   rA[2];
    uint32_t rBh[NBU], rBl[NBU];

    float acc[MI][NI][4];
#pragma unroll
    for (int i = 0; i < MI; i++)
#pragma unroll
        for (int j = 0; j < NI; j++) {
            acc[i][j][0] = 0.f; acc[i][j][1] = 0.f; acc[i][j][2] = 0.f; acc[i][j][3] = 0.f;
        }

    auto loadA = [&](int k0) {
#pragma unroll
        for (int u = 0; u < 2; u++) {
            int idx = tid + u * 256;
            int row = idx >> 2;
            int c4  = idx & 3;
            float4 v = make_float4(0.f, 0.f, 0.f, 0.f);
            int gm = m0 + row;
            if (gm < M) {
                v = *(const float4*)(A + (size_t)gm * K + k0 + c4 * 4);
                if (FUSE) {
                    int kk = k0 + c4 * 4;
                    v.x = fmaxf(v.x + bias[kk + 0], 0.f);
                    v.y = fmaxf(v.y + bias[kk + 1], 0.f);
                    v.z = fmaxf(v.z + bias[kk + 2], 0.f);
                    v.w = fmaxf(v.w + bias[kk + 3], 0.f);
                }
            }
            rA[u] = v;
        }
    };
    auto loadB = [&](int k0) {
#pragma unroll
        for (int u = 0; u < NBU; u++) {
            int idx = tid + u * 256;
            int n = idx >> 3;
            int c = idx & 7;
            rBh[u] = *(const uint32_t*)(BThi + (size_t)n * K + k0 + c * 2);
            rBl[u] = *(const uint32_t*)(BTlo + (size_t)n * K + k0 + c * 2);
        }
    };
    auto storeTile = [&](int buf) {
#pragma unroll
        for (int u = 0; u < 2; u++) {
            int idx = tid + u * 256;
            int row = idx >> 2;
            int c4  = idx & 3;
            float4 v = rA[u];
            __nv_bfloat162 h0 = __floats2bfloat162_rn(v.x, v.y);
            __nv_bfloat162 h1 = __floats2bfloat162_rn(v.z, v.w);
            __nv_bfloat162 l0 = __floats2bfloat162_rn(v.x - __bfloat162float(h0.x),
                                                      v.y - __bfloat162float(h0.y));
            __nv_bfloat162 l1 = __floats2bfloat162_rn(v.z - __bfloat162float(h1.x),
                                                      v.w - __bfloat162float(h1.y));
            *(__nv_bfloat162*)&sAhi[buf][row][c4 * 4]     = h0;
            *(__nv_bfloat162*)&sAhi[buf][row][c4 * 4 + 2] = h1;
            *(__nv_bfloat162*)&sAlo[buf][row][c4 * 4]     = l0;
            *(__nv_bfloat162*)&sAlo[buf][row][c4 * 4 + 2] = l1;
        }
#pragma unroll
        for (int u = 0; u < NBU; u++) {
            int idx = tid + u * 256;
            int n = idx >> 3;
            int c = idx & 7;
            *(uint32_t*)&sBhi[buf][n][c * 2] = rBh[u];
            *(uint32_t*)&sBlo[buf][n][c * 2] = rBl[u];
        }
    };

    const int nIter = K / BK;
    loadA(0); loadB(0);
    storeTile(0);
    __syncthreads();

    for (int it = 0; it < nIter; ++it) {
        if (it + 1 < nIter) { loadA((it + 1) * BK); loadB((it + 1) * BK); }
        const int p = it & 1;

        uint32_t ah[MI][4], al[MI][4];
#pragma unroll
        for (int mi = 0; mi < MI; mi++) {
            int r = wm + mi * 16 + gid;
            ah[mi][0] = *(const uint32_t*)&sAhi[p][r][2 * tig];
            ah[mi][1] = *(const uint32_t*)&sAhi[p][r + 8][2 * tig];
            ah[mi][2] = *(const uint32_t*)&sAhi[p][r][2 * tig + 8];
            ah[mi][3] = *(const uint32_t*)&sAhi[p][r + 8][2 * tig + 8];
            al[mi][0] = *(const uint32_t*)&sAlo[p][r][2 * tig];
            al[mi][1] = *(const uint32_t*)&sAlo[p][r + 8][2 * tig];
            al[mi][2] = *(const uint32_t*)&sAlo[p][r][2 * tig + 8];
            al[mi][3] = *(const uint32_t*)&sAlo[p][r + 8][2 * tig + 8];
        }
        uint32_t bh[NI][2], bl[NI][2];
#pragma unroll
        for (int ni = 0; ni < NI; ni++) {
            int n = wn + ni * 8 + gid;
            bh[ni][0] = *(const uint32_t*)&sBhi[p][n][2 * tig];
            bh[ni][1] = *(const uint32_t*)&sBhi[p][n][2 * tig + 8];
            bl[ni][0] = *(const uint32_t*)&sBlo[p][n][2 * tig];
            bl[ni][1] = *(const uint32_t*)&sBlo[p][n][2 * tig + 8];
        }
#pragma unroll
        for (int mi = 0; mi < MI; mi++)
#pragma unroll
            for (int ni = 0; ni < NI; ni++) {
                MMA_BF16(acc[mi][ni], ah[mi], bh[ni]);
                MMA_BF16(acc[mi][ni], ah[mi], bl[ni]);
                MMA_BF16(acc[mi][ni], al[mi], bh[ni]);
            }

        if (it + 1 < nIter) storeTile((it + 1) & 1);
        __syncthreads();
    }

#pragma unroll
    for (int mi = 0; mi < MI; mi++) {
        int r0 = m0 + wm + mi * 16 + gid;
        int r1 = r0 + 8;
        float s0 = (r0 < M) ? rowscale[r0] : 0.f;
        float s1 = (r1 < M) ? rowscale[r1] : 0.f;
#pragma unroll
        for (int ni = 0; ni < NI; ni++) {
            int col = wn + ni * 8 + 2 * tig;
            if (r0 < M)
                *(float2*)(C + (size_t)r0 * BN + col) =
                    make_float2(acc[mi][ni][0] * s0, acc[mi][ni][1] * s0);
            if (r1 < M)
                *(float2*)(C + (size_t)r1 * BN + col) =
                    make_float2(acc[mi][ni][2] * s1, acc[mi][ni][3] * s1);
        }
    }
}

// ---------------- CSR gather aggregation (inputs pre-scaled by dinv) ----------------
// node range [nodeBase, nodeEnd)
__global__ void gather128_kernel(const float4* __restrict__ hs, const int* __restrict__ csrc,
                                 const int* __restrict__ rowptr, const float* __restrict__ dinv,
                                 float4* __restrict__ out, int nodeBase, int nodeEnd) {
    int w = nodeBase + ((blockIdx.x * blockDim.x + threadIdx.x) >> 5);
    if (w >= nodeEnd) return;
    int lane = threadIdx.x & 31;
    int begin = rowptr[w], end = rowptr[w + 1];
    float4 a0 = __ldg(&hs[(size_t)w * 32 + lane]);
    float4 a1 = make_float4(0.f, 0.f, 0.f, 0.f);
    float4 a2 = make_float4(0.f, 0.f, 0.f, 0.f);
    float4 a3 = make_float4(0.f, 0.f, 0.f, 0.f);
    int j = begin;
    for (; j + 4 <= end; j += 4) {
        int s0 = __ldg(&csrc[j]);
        int s1 = __ldg(&csrc[j + 1]);
        int s2 = __ldg(&csrc[j + 2]);
        int s3 = __ldg(&csrc[j + 3]);
        float4 v0 = __ldg(&hs[(size_t)s0 * 32 + lane]);
        float4 v1 = __ldg(&hs[(size_t)s1 * 32 + lane]);
        float4 v2 = __ldg(&hs[(size_t)s2 * 32 + lane]);
        float4 v3 = __ldg(&hs[(size_t)s3 * 32 + lane]);
        a0.x += v0.x; a0.y += v0.y; a0.z += v0.z; a0.w += v0.w;
        a1.x += v1.x; a1.y += v1.y; a1.z += v1.z; a1.w += v1.w;
        a2.x += v2.x; a2.y += v2.y; a2.z += v2.z; a2.w += v2.w;
        a3.x += v3.x; a3.y += v3.y; a3.z += v3.z; a3.w += v3.w;
    }
    for (; j < end; ++j) {
        int s0 = __ldg(&csrc[j]);
        float4 v0 = __ldg(&hs[(size_t)s0 * 32 + lane]);
        a0.x += v0.x; a0.y += v0.y; a0.z += v0.z; a0.w += v0.w;
    }
    float dv = dinv[w];
    float4 r;
    r.x = dv * ((a0.x + a1.x) + (a2.x + a3.x));
    r.y = dv * ((a0.y + a1.y) + (a2.y + a3.y));
    r.z = dv * ((a0.z + a1.z) + (a2.z + a3.z));
    r.w = dv * ((a0.w + a1.w) + (a2.w + a3.w));
    out[(size_t)w * 32 + lane] = r;
}

__global__ void gather64_kernel(const float2* __restrict__ hs, const int* __restrict__ csrc,
                                const int* __restrict__ rowptr, const float* __restrict__ dinv,
                                const float* __restrict__ b2, float2* __restrict__ out) {
    int w = (blockIdx.x * blockDim.x + threadIdx.x) >> 5;
    if (w >= NN) return;
    int lane = threadIdx.x & 31;
    int begin = rowptr[w], end = rowptr[w + 1];
    float2 a0 = __ldg(&hs[(size_t)w * 32 + lane]);
    float2 a1 = make_float2(0.f, 0.f);
    float2 a2 = make_float2(0.f, 0.f);
    float2 a3 = make_float2(0.f, 0.f);
    int j = begin;
    for (; j + 4 <= end; j += 4) {
        int s0 = __ldg(&csrc[j]);
        int s1 = __ldg(&csrc[j + 1]);
        int s2 = __ldg(&csrc[j + 2]);
        int s3 = __ldg(&csrc[j + 3]);
        float2 v0 = __ldg(&hs[(size_t)s0 * 32 + lane]);
        float2 v1 = __ldg(&hs[(size_t)s1 * 32 + lane]);
        float2 v2 = __ldg(&hs[(size_t)s2 * 32 + lane]);
        float2 v3 = __ldg(&hs[(size_t)s3 * 32 + lane]);
        a0.x += v0.x; a0.y += v0.y;
        a1.x += v1.x; a1.y += v1.y;
        a2.x += v2.x; a2.y += v2.y;
        a3.x += v3.x; a3.y += v3.y;
    }
    for (; j < end; ++j) {
        int s0 = __ldg(&csrc[j]);
        float2 v0 = __ldg(&hs[(size_t)s0 * 32 + lane]);
        a0.x += v0.x; a0.y += v0.y;
    }
    float dv = dinv[w];
    float2 r;
    r.x = dv * ((a0.x + a1.x) + (a2.x + a3.x)) + b2[lane * 2 + 0];
    r.y = dv * ((a0.y + a1.y) + (a2.y + a3.y)) + b2[lane * 2 + 1];
    out[(size_t)w * 32 + lane] = r;
}

// ---------------- launch ----------------
extern "C" void kernel_launch(void* const* d_in, const int* in_sizes, int n_in,
                              void* d_out, int out_size) {
    const float* x   = (const float*)d_in[0];
    const int*   ei  = (const int*)d_in[1];   // int32 (JAX x64 disabled)
    const float* W1  = (const float*)d_in[2];
    const float* b1  = (const float*)d_in[3];
    const float* W2  = (const float*)d_in[4];
    const float* b2  = (const float*)d_in[5];
    float*       out = (float*)d_out;

    const int E = in_sizes[1] / 2;
    const int* src = ei;
    const int* dst = ei + E;

    void* p;
    cudaGetSymbolAddress(&p, g_h1);     float* h1     = (float*)p;
    cudaGetSymbolAddress(&p, g_agg1);   float* agg1   = (float*)p;
    cudaGetSymbolAddress(&p, g_h2);     float* h2     = (float*)p;
    cudaGetSymbolAddress(&p, g_dinv);   float* dinv   = (float*)p;
    cudaGetSymbolAddress(&p, g_deg);    int*   deg    = (int*)p;
    cudaGetSymbolAddress(&p, g_rowptr); int*   rowptr = (int*)p;
    cudaGetSymbolAddress(&p, g_fill);   int*   fill   = (int*)p;
    cudaGetSymbolAddress(&p, g_csrc);   int*   csrc   = (int*)p;
    cudaGetSymbolAddress(&p, g_bsum);   int*   bsum   = (int*)p;
    cudaGetSymbolAddress(&p, g_boff);   int*   boff   = (int*)p;
    cudaGetSymbolAddress(&p, g_w1hi);   __nv_bfloat16* w1hi = (__nv_bfloat16*)p;
    cudaGetSymbolAddress(&p, g_w1lo);   __nv_bfloat16* w1lo = (__nv_bfloat16*)p;
    cudaGetSymbolAddress(&p, g_w2hi);   __nv_bfloat16* w2hi = (__nv_bfloat16*)p;
    cudaGetSymbolAddress(&p, g_w2lo);   __nv_bfloat16* w2lo = (__nv_bfloat16*)p;

    static cudaStream_t s1 = nullptr;
    static cudaEvent_t  eDinv = nullptr, eGemm1 = nullptr, eG0 = nullptr, eH0 = nullptr;
    if (!s1) {
        cudaStreamCreateWithFlags(&s1, cudaStreamNonBlocking);
        cudaEventCreateWithFlags(&eDinv,  cudaEventDisableTiming);
        cudaEventCreateWithFlags(&eGemm1, cudaEventDisableTiming);
        cudaEventCreateWithFlags(&eG0,    cudaEventDisableTiming);
        cudaEventCreateWithFlags(&eH0,    cudaEventDisableTiming);
    }

    // ---- main: prep (deg=0 + wsplit) -> degree counts -> dinv/bsum ----
    prep_kernel<<<(NN + 255) / 256, 256>>>(deg, W1, W2, w1hi, w1lo, w2hi, w2lo);
    deg_count_kernel<<<(E + 255) / 256, 256>>>(dst, deg, E);
    scan_reduce_kernel<<<SC_NB, SC_T>>>(deg, bsum, dinv, NN);
    cudaEventRecord(eDinv, 0);

    // ---- s1: GEMM1 overlaps CSR build ----
    cudaStreamWaitEvent(s1, eDinv, 0);
    mma_gemm_kernel<HID, 2, 4, false><<<(NN + 127) / 128, 256, 0, s1>>>(
        x, w1hi, w1lo, nullptr, dinv, h1, NN, IND);
    cudaEventRecord(eGemm1, s1);

    // ---- main: finish CSR ----
    scan_offsets_kernel<<<1, 128>>>(bsum, boff, rowptr, NN);
    scan_write_kernel<<<SC_NB, SC_T>>>(deg, boff, rowptr, fill, NN);
    fill_kernel<<<(E + 255) / 256, 256>>>(src, dst, fill, csrc, E);

    // ---- chunked tail pipeline ----
    const int gwarps = (CHUNK * 32 + 255) / 256;           // blocks per gather128 chunk
    const int g2grid = (CHUNK + 127) / 128;                // blocks per GEMM2 chunk

    cudaStreamWaitEvent(0, eGemm1, 0);
    // gather128 chunk0
    gather128_kernel<<<gwarps, 256>>>((const float4*)h1, csrc, rowptr, dinv, (float4*)agg1, 0, CHUNK);
    cudaEventRecord(eG0, 0);

    // s1: GEMM2 chunk0 overlaps gather128 chunk1
    cudaStreamWaitEvent(s1, eG0, 0);
    mma_gemm_kernel<OUTD, 4, 2, true><<<g2grid, 256, 0, s1>>>(
        agg1, w2hi, w2lo, b1, dinv, h2, CHUNK, HID);
    cudaEventRecord(eH0, s1);

    // main: gather128 chunk1, then GEMM2 chunk1
    gather128_kernel<<<gwarps, 256>>>((const float4*)h1, csrc, rowptr, dinv, (float4*)agg1, CHUNK, NN);
    mma_gemm_kernel<OUTD, 4, 2, true><<<g2grid, 256>>>(
        agg1 + (size_t)CHUNK * HID, w2hi, w2lo, b1, dinv + CHUNK,
        h2 + (size_t)CHUNK * OUTD, NN - CHUNK, HID);

    // join, final gather
    cudaStreamWaitEvent(0, eH0, 0);
    gather64_kernel<<<(NN * 32 + 255) / 256, 256>>>((const float2*)h2, csrc, rowptr, dinv, b2, (float2*)out);
}

// round 9
// speedup vs baseline: 1.4877x; 1.4877x over previous
#include <cuda_runtime.h>
#include <cuda_bf16.h>
#include <cstdint>

#define NN   50000
#define IND  256
#define HID  128
#define OUTD 64
#define EMAX 800000

// scan config: small chunks for full-chip occupancy
#define SC_T     256
#define SC_I     2
#define SC_CHUNK (SC_T * SC_I)                     // 512
#define SC_NB    ((NN + SC_CHUNK - 1) / SC_CHUNK)  // 98

// -------- device scratch --------
__device__ float g_h1[NN * HID];
__device__ float g_agg1[NN * HID];
__device__ float g_h2[NN * OUTD];
__device__ float g_dinv[NN];
__device__ int   g_deg[NN];          // raw in-edge counts (no self loop)
__device__ int   g_rowptr[NN + 1];
__device__ int   g_fill[NN];
__device__ int   g_csrc[EMAX];
__device__ int   g_bsum[SC_NB];
__device__ int   g_boff[SC_NB];
__device__ __nv_bfloat16 g_w1hi[HID * IND];
__device__ __nv_bfloat16 g_w1lo[HID * IND];
__device__ __nv_bfloat16 g_w2hi[OUTD * HID];
__device__ __nv_bfloat16 g_w2lo[OUTD * HID];

// ---------------- prep: deg=0 + both weight splits in ONE launch ----------------
__global__ void prep_kernel(int* __restrict__ deg,
                            const float* __restrict__ W1, const float* __restrict__ W2,
                            __nv_bfloat16* __restrict__ T1h, __nv_bfloat16* __restrict__ T1l,
                            __nv_bfloat16* __restrict__ T2h, __nv_bfloat16* __restrict__ T2l) {
    int i = blockIdx.x * blockDim.x + threadIdx.x;
    if (i < NN) deg[i] = 0;
    const int n1 = IND * HID;
    const int n2 = HID * OUTD;
    if (i < n1) {
        int k = i / HID, n = i % HID;
        float v = W1[i];
        __nv_bfloat16 h = __float2bfloat16(v);
        T1h[(size_t)n * IND + k] = h;
        T1l[(size_t)n * IND + k] = __float2bfloat16(v - __bfloat162float(h));
    } else if (i < n1 + n2) {
        int j = i - n1;
        int k = j / OUTD, n = j % OUTD;
        float v = W2[j];
        __nv_bfloat16 h = __float2bfloat16(v);
        T2h[(size_t)n * HID + k] = h;
        T2l[(size_t)n * HID + k] = __float2bfloat16(v - __bfloat162float(h));
    }
}

__global__ void deg_count_kernel(const int* __restrict__ dst, int* __restrict__ deg, int E) {
    int i = blockIdx.x * blockDim.x + threadIdx.x;
    if (i < E) atomicAdd(&deg[dst[i]], 1);
}

// ---------------- scan chain (98 blocks, coalesced) ----------------
__global__ void scan_reduce_kernel(const int* __restrict__ deg, int* __restrict__ bsum,
                                   float* __restrict__ dinv, int n) {
    __shared__ int ws[SC_T / 32];
    int b = blockIdx.x, tid = threadIdx.x;
    int base = b * SC_CHUNK;
    int s = 0;
#pragma unroll
    for (int u = 0; u < SC_I; u++) {
        int i = base + u * SC_T + tid;
        if (i < n) {
            int c = deg[i];
            s += c;
            dinv[i] = rsqrtf((float)(c + 1));
        }
    }
#pragma unroll
    for (int d = 16; d; d >>= 1) s += __shfl_down_sync(0xffffffffu, s, d);
    if ((tid & 31) == 0) ws[tid >> 5] = s;
    __syncthreads();
    if (tid < 32) {
        int v = (tid < SC_T / 32) ? ws[tid] : 0;
#pragma unroll
        for (int d = 16; d; d >>= 1) v += __shfl_down_sync(0xffffffffu, v, d);
        if (tid == 0) bsum[b] = v;
    }
}

// 128-thread scan over SC_NB (=98) block sums
__global__ void scan_offsets_kernel(const int* __restrict__ bsum, int* __restrict__ boff,
                                    int* __restrict__ rowptr, int n) {
    __shared__ int ws[4];
    int tid = threadIdx.x;
    int lane = tid & 31, wid = tid >> 5;
    int v = (tid < SC_NB) ? bsum[tid] : 0;
    int x = v;
#pragma unroll
    for (int d = 1; d < 32; d <<= 1) {
        int y = __shfl_up_sync(0xffffffffu, x, d);
        if (lane >= d) x += y;
    }
    if (lane == 31) ws[wid] = x;
    __syncthreads();
    if (tid == 0) {
        int acc = 0;
#pragma unroll
        for (int k = 0; k < 4; k++) { int t = ws[k]; ws[k] = acc; acc += t; }
        rowptr[n] = acc;
    }
    __syncthreads();
    if (tid < SC_NB) boff[tid] = x - v + ws[wid];
}

// writes rowptr AND fill (atomic cursor copy)
__global__ void scan_write_kernel(const int* __restrict__ deg, const int* __restrict__ boff,
                                  int* __restrict__ rowptr, int* __restrict__ fill, int n) {
    __shared__ int sbuf[SC_CHUNK];
    __shared__ int ws[SC_T / 32];
    int b = blockIdx.x, tid = threadIdx.x;
    int lane = tid & 31, wid = tid >> 5;
    int base = b * SC_CHUNK;

#pragma unroll
    for (int u = 0; u < SC_I; u++) {
        int i = base + u * SC_T + tid;
        sbuf[u * SC_T + tid] = (i < n) ? deg[i] : 0;
    }
    __syncthreads();

    int v[SC_I];
    int tot = 0;
#pragma unroll
    for (int u = 0; u < SC_I; u++) {
        int d = sbuf[tid * SC_I + u];
        v[u] = tot;
        tot += d;
    }
    int x = tot;
#pragma unroll
    for (int d = 1; d < 32; d <<= 1) {
        int y = __shfl_up_sync(0xffffffffu, x, d);
        if (lane >= d) x += y;
    }
    if (lane == 31) ws[wid] = x;
    __syncthreads();
    if (wid == 0) {
        int y = (lane < SC_T / 32) ? ws[lane] : 0;
#pragma unroll
        for (int d = 1; d < 32; d <<= 1) {
            int z = __shfl_up_sync(0xffffffffu, y, d);
            if (lane >= d) y += z;
        }
        if (lane < SC_T / 32) ws[lane] = y;
    }
    __syncthreads();
    int off = boff[b] + (x - tot) + (wid ? ws[wid - 1] : 0);
#pragma unroll
    for (int u = 0; u < SC_I; u++) sbuf[tid * SC_I + u] = off + v[u];
    __syncthreads();

#pragma unroll
    for (int u = 0; u < SC_I; u++) {
        int i = base + u * SC_T + tid;
        if (i < n) {
            int r = sbuf[u * SC_T + tid];
            rowptr[i] = r;
            fill[i] = r;
        }
    }
}

__global__ void fill_kernel(const int* __restrict__ src, const int* __restrict__ dst,
                            int* __restrict__ fill, int* __restrict__ csrc, int E) {
    int i = blockIdx.x * blockDim.x + threadIdx.x;
    if (i >= E) return;
    int pos = atomicAdd(&fill[dst[i]], 1);
    csrc[pos] = src[i];
}

// ---------------- split-bf16 tensor-core GEMM ----------------
#define MMA_BF16(c, a, b) asm volatile( \
    "mma.sync.aligned.m16n8k16.row.col.f32.bf16.bf16.f32 " \
    "{%0,%1,%2,%3}, {%4,%5,%6,%7}, {%8,%9}, {%0,%1,%2,%3};" \
    : "+f"((c)[0]), "+f"((c)[1]), "+f"((c)[2]), "+f"((c)[3]) \
    : "r"((a)[0]), "r"((a)[1]), "r"((a)[2]), "r"((a)[3]), "r"((b)[0]), "r"((b)[1]))

template<int BN, int WGM, int WGN, bool FUSE>
__global__ __launch_bounds__(256)
void mma_gemm_kernel(const float* __restrict__ A,
                     const __nv_bfloat16* __restrict__ BThi,
                     const __nv_bfloat16* __restrict__ BTlo,
                     const float* __restrict__ bias,
                     const float* __restrict__ rowscale,
                     float* __restrict__ C, int M, int K) {
    constexpr int BM = 128, BK = 16, BKP = 20;
    constexpr int MI = BM / (WGM * 16);
    constexpr int NI = BN / (WGN * 8);
    constexpr int NBU = BN * 8 / 256;

    __shared__ __nv_bfloat16 sAhi[2][BM][BKP], sAlo[2][BM][BKP];
    __shared__ __nv_bfloat16 sBhi[2][BN][BKP], sBlo[2][BN][BKP];

    const int tid  = threadIdx.x;
    const int m0   = blockIdx.x * BM;
    const int w    = tid >> 5, lane = tid & 31;
    const int wm   = (w / WGN) * MI * 16;
    const int wn   = (w % WGN) * NI * 8;
    const int gid  = lane >> 2, tig = lane & 3;

    float4   rA[2];
    uint32_t rBh[NBU], rBl[NBU];

    float acc[MI][NI][4];
#pragma unroll
    for (int i = 0; i < MI; i++)
#pragma unroll
        for (int j = 0; j < NI; j++) {
            acc[i][j][0] = 0.f; acc[i][j][1] = 0.f; acc[i][j][2] = 0.f; acc[i][j][3] = 0.f;
        }

    auto loadA = [&](int k0) {
#pragma unroll
        for (int u = 0; u < 2; u++) {
            int idx = tid + u * 256;
            int row = idx >> 2;
            int c4  = idx & 3;
            float4 v = make_float4(0.f, 0.f, 0.f, 0.f);
            int gm = m0 + row;
            if (gm < M) {
                v = *(const float4*)(A + (size_t)gm * K + k0 + c4 * 4);
                if (FUSE) {
                    int kk = k0 + c4 * 4;
                    v.x = fmaxf(v.x + bias[kk + 0], 0.f);
                    v.y = fmaxf(v.y + bias[kk + 1], 0.f);
                    v.z = fmaxf(v.z + bias[kk + 2], 0.f);
                    v.w = fmaxf(v.w + bias[kk + 3], 0.f);
                }
            }
            rA[u] = v;
        }
    };
    auto loadB = [&](int k0) {
#pragma unroll
        for (int u = 0; u < NBU; u++) {
            int idx = tid + u * 256;
            int n = idx >> 3;
            int c = idx & 7;
            rBh[u] = *(const uint32_t*)(BThi + (size_t)n * K + k0 + c * 2);
            rBl[u] = *(const uint32_t*)(BTlo + (size_t)n * K + k0 + c * 2);
        }
    };
    auto storeTile = [&](int buf) {
#pragma unroll
        for (int u = 0; u < 2; u++) {
            int idx = tid + u * 256;
            int row = idx >> 2;
            int c4  = idx & 3;
            float4 v = rA[u];
            __nv_bfloat162 h0 = __floats2bfloat162_rn(v.x, v.y);
            __nv_bfloat162 h1 = __floats2bfloat162_rn(v.z, v.w);
            __nv_bfloat162 l0 = __floats2bfloat162_rn(v.x - __bfloat162float(h0.x),
                                                      v.y - __bfloat162float(h0.y));
            __nv_bfloat162 l1 = __floats2bfloat162_rn(v.z - __bfloat162float(h1.x),
                                                      v.w - __bfloat162float(h1.y));
            *(__nv_bfloat162*)&sAhi[buf][row][c4 * 4]     = h0;
            *(__nv_bfloat162*)&sAhi[buf][row][c4 * 4 + 2] = h1;
            *(__nv_bfloat162*)&sAlo[buf][row][c4 * 4]     = l0;
            *(__nv_bfloat162*)&sAlo[buf][row][c4 * 4 + 2] = l1;
        }
#pragma unroll
        for (int u = 0; u < NBU; u++) {
            int idx = tid + u * 256;
            int n = idx >> 3;
            int c = idx & 7;
            *(uint32_t*)&sBhi[buf][n][c * 2] = rBh[u];
            *(uint32_t*)&sBlo[buf][n][c * 2] = rBl[u];
        }
    };

    const int nIter = K / BK;
    loadA(0); loadB(0);
    storeTile(0);
    __syncthreads();

    for (int it = 0; it < nIter; ++it) {
        if (it + 1 < nIter) { loadA((it + 1) * BK); loadB((it + 1) * BK); }
        const int p = it & 1;

        uint32_t ah[MI][4], al[MI][4];
#pragma unroll
        for (int mi = 0; mi < MI; mi++) {
            int r = wm + mi * 16 + gid;
            ah[mi][0] = *(const uint32_t*)&sAhi[p][r][2 * tig];
            ah[mi][1] = *(const uint32_t*)&sAhi[p][r + 8][2 * tig];
            ah[mi][2] = *(const uint32_t*)&sAhi[p][r][2 * tig + 8];
            ah[mi][3] = *(const uint32_t*)&sAhi[p][r + 8][2 * tig + 8];
            al[mi][0] = *(const uint32_t*)&sAlo[p][r][2 * tig];
            al[mi][1] = *(const uint32_t*)&sAlo[p][r + 8][2 * tig];
            al[mi][2] = *(const uint32_t*)&sAlo[p][r][2 * tig + 8];
            al[mi][3] = *(const uint32_t*)&sAlo[p][r + 8][2 * tig + 8];
        }
        uint32_t bh[NI][2], bl[NI][2];
#pragma unroll
        for (int ni = 0; ni < NI; ni++) {
            int n = wn + ni * 8 + gid;
            bh[ni][0] = *(const uint32_t*)&sBhi[p][n][2 * tig];
            bh[ni][1] = *(const uint32_t*)&sBhi[p][n][2 * tig + 8];
            bl[ni][0] = *(const uint32_t*)&sBlo[p][n][2 * tig];
            bl[ni][1] = *(const uint32_t*)&sBlo[p][n][2 * tig + 8];
        }
#pragma unroll
        for (int mi = 0; mi < MI; mi++)
#pragma unroll
            for (int ni = 0; ni < NI; ni++) {
                MMA_BF16(acc[mi][ni], ah[mi], bh[ni]);
                MMA_BF16(acc[mi][ni], ah[mi], bl[ni]);
                MMA_BF16(acc[mi][ni], al[mi], bh[ni]);
            }

        if (it + 1 < nIter) storeTile((it + 1) & 1);
        __syncthreads();
    }

#pragma unroll
    for (int mi = 0; mi < MI; mi++) {
        int r0 = m0 + wm + mi * 16 + gid;
        int r1 = r0 + 8;
        float s0 = (r0 < M) ? rowscale[r0] : 0.f;
        float s1 = (r1 < M) ? rowscale[r1] : 0.f;
#pragma unroll
        for (int ni = 0; ni < NI; ni++) {
            int col = wn + ni * 8 + 2 * tig;
            if (r0 < M)
                *(float2*)(C + (size_t)r0 * BN + col) =
                    make_float2(acc[mi][ni][0] * s0, acc[mi][ni][1] * s0);
            if (r1 < M)
                *(float2*)(C + (size_t)r1 * BN + col) =
                    make_float2(acc[mi][ni][2] * s1, acc[mi][ni][3] * s1);
        }
    }
}

// ---------------- CSR gather aggregation (inputs pre-scaled by dinv) ----------------
__global__ void gather128_kernel(const float4* __restrict__ hs, const int* __restrict__ csrc,
                                 const int* __restrict__ rowptr, const float* __restrict__ dinv,
                                 float4* __restrict__ out) {
    int w = (blockIdx.x * blockDim.x + threadIdx.x) >> 5;
    if (w >= NN) return;
    int lane = threadIdx.x & 31;
    int begin = rowptr[w], end = rowptr[w + 1];
    float4 a0 = __ldg(&hs[(size_t)w * 32 + lane]);
    float4 a1 = make_float4(0.f, 0.f, 0.f, 0.f);
    float4 a2 = make_float4(0.f, 0.f, 0.f, 0.f);
    float4 a3 = make_float4(0.f, 0.f, 0.f, 0.f);
    int j = begin;
    for (; j + 4 <= end; j += 4) {
        int s0 = __ldg(&csrc[j]);
        int s1 = __ldg(&csrc[j + 1]);
        int s2 = __ldg(&csrc[j + 2]);
        int s3 = __ldg(&csrc[j + 3]);
        float4 v0 = __ldg(&hs[(size_t)s0 * 32 + lane]);
        float4 v1 = __ldg(&hs[(size_t)s1 * 32 + lane]);
        float4 v2 = __ldg(&hs[(size_t)s2 * 32 + lane]);
        float4 v3 = __ldg(&hs[(size_t)s3 * 32 + lane]);
        a0.x += v0.x; a0.y += v0.y; a0.z += v0.z; a0.w += v0.w;
        a1.x += v1.x; a1.y += v1.y; a1.z += v1.z; a1.w += v1.w;
        a2.x += v2.x; a2.y += v2.y; a2.z += v2.z; a2.w += v2.w;
        a3.x += v3.x; a3.y += v3.y; a3.z += v3.z; a3.w += v3.w;
    }
    for (; j < end; ++j) {
        int s0 = __ldg(&csrc[j]);
        float4 v0 = __ldg(&hs[(size_t)s0 * 32 + lane]);
        a0.x += v0.x; a0.y += v0.y; a0.z += v0.z; a0.w += v0.w;
    }
    float dv = dinv[w];
    float4 r;
    r.x = dv * ((a0.x + a1.x) + (a2.x + a3.x));
    r.y = dv * ((a0.y + a1.y) + (a2.y + a3.y));
    r.z = dv * ((a0.z + a1.z) + (a2.z + a3.z));
    r.w = dv * ((a0.w + a1.w) + (a2.w + a3.w));
    out[(size_t)w * 32 + lane] = r;
}

__global__ void gather64_kernel(const float2* __restrict__ hs, const int* __restrict__ csrc,
                                const int* __restrict__ rowptr, const float* __restrict__ dinv,
                                const float* __restrict__ b2, float2* __restrict__ out) {
    int w = (blockIdx.x * blockDim.x + threadIdx.x) >> 5;
    if (w >= NN) return;
    int lane = threadIdx.x & 31;
    int begin = rowptr[w], end = rowptr[w + 1];
    float2 a0 = __ldg(&hs[(size_t)w * 32 + lane]);
    float2 a1 = make_float2(0.f, 0.f);
    float2 a2 = make_float2(0.f, 0.f);
    float2 a3 = make_float2(0.f, 0.f);
    int j = begin;
    for (; j + 4 <= end; j += 4) {
        int s0 = __ldg(&csrc[j]);
        int s1 = __ldg(&csrc[j + 1]);
        int s2 = __ldg(&csrc[j + 2]);
        int s3 = __ldg(&csrc[j + 3]);
        float2 v0 = __ldg(&hs[(size_t)s0 * 32 + lane]);
        float2 v1 = __ldg(&hs[(size_t)s1 * 32 + lane]);
        float2 v2 = __ldg(&hs[(size_t)s2 * 32 + lane]);
        float2 v3 = __ldg(&hs[(size_t)s3 * 32 + lane]);
        a0.x += v0.x; a0.y += v0.y;
        a1.x += v1.x; a1.y += v1.y;
        a2.x += v2.x; a2.y += v2.y;
        a3.x += v3.x; a3.y += v3.y;
    }
    for (; j < end; ++j) {
        int s0 = __ldg(&csrc[j]);
        float2 v0 = __ldg(&hs[(size_t)s0 * 32 + lane]);
        a0.x += v0.x; a0.y += v0.y;
    }
    float dv = dinv[w];
    float2 r;
    r.x = dv * ((a0.x + a1.x) + (a2.x + a3.x)) + b2[lane * 2 + 0];
    r.y = dv * ((a0.y + a1.y) + (a2.y + a3.y)) + b2[lane * 2 + 1];
    out[(size_t)w * 32 + lane] = r;
}

// ---------------- launch (R7 topology) ----------------
extern "C" void kernel_launch(void* const* d_in, const int* in_sizes, int n_in,
                              void* d_out, int out_size) {
    const float* x   = (const float*)d_in[0];
    const int*   ei  = (const int*)d_in[1];   // int32 (JAX x64 disabled)
    const float* W1  = (const float*)d_in[2];
    const float* b1  = (const float*)d_in[3];
    const float* W2  = (const float*)d_in[4];
    const float* b2  = (const float*)d_in[5];
    float*       out = (float*)d_out;

    const int E = in_sizes[1] / 2;
    const int* src = ei;
    const int* dst = ei + E;

    void* p;
    cudaGetSymbolAddress(&p, g_h1);     float* h1     = (float*)p;
    cudaGetSymbolAddress(&p, g_agg1);   float* agg1   = (float*)p;
    cudaGetSymbolAddress(&p, g_h2);     float* h2     = (float*)p;
    cudaGetSymbolAddress(&p, g_dinv);   float* dinv   = (float*)p;
    cudaGetSymbolAddress(&p, g_deg);    int*   deg    = (int*)p;
    cudaGetSymbolAddress(&p, g_rowptr); int*   rowptr = (int*)p;
    cudaGetSymbolAddress(&p, g_fill);   int*   fill   = (int*)p;
    cudaGetSymbolAddress(&p, g_csrc);   int*   csrc   = (int*)p;
    cudaGetSymbolAddress(&p, g_bsum);   int*   bsum   = (int*)p;
    cudaGetSymbolAddress(&p, g_boff);   int*   boff   = (int*)p;
    cudaGetSymbolAddress(&p, g_w1hi);   __nv_bfloat16* w1hi = (__nv_bfloat16*)p;
    cudaGetSymbolAddress(&p, g_w1lo);   __nv_bfloat16* w1lo = (__nv_bfloat16*)p;
    cudaGetSymbolAddress(&p, g_w2hi);   __nv_bfloat16* w2hi = (__nv_bfloat16*)p;
    cudaGetSymbolAddress(&p, g_w2lo);   __nv_bfloat16* w2lo = (__nv_bfloat16*)p;

    static cudaStream_t s1 = nullptr;
    static cudaEvent_t  eDinv = nullptr, eGemm1 = nullptr;
    if (!s1) {
        cudaStreamCreateWithFlags(&s1, cudaStreamNonBlocking);
        cudaEventCreateWithFlags(&eDinv,  cudaEventDisableTiming);
        cudaEventCreateWithFlags(&eGemm1, cudaEventDisableTiming);
    }

    const int warpsGrid = (NN * 32 + 255) / 256;
    const int gemmGrid  = (NN + 127) / 128;

    // ---- main: prep (deg=0 + wsplit) -> degree counts -> dinv/bsum ----
    prep_kernel<<<(NN + 255) / 256, 256>>>(deg, W1, W2, w1hi, w1lo, w2hi, w2lo);
    deg_count_kernel<<<(E + 255) / 256, 256>>>(dst, deg, E);
    scan_reduce_kernel<<<SC_NB, SC_T>>>(deg, bsum, dinv, NN);
    cudaEventRecord(eDinv, 0);

    // ---- s1: GEMM1 overlaps CSR build ----
    cudaStreamWaitEvent(s1, eDinv, 0);
    mma_gemm_kernel<HID, 2, 4, false><<<gemmGrid, 256, 0, s1>>>(
        x, w1hi, w1lo, nullptr, dinv, h1, NN, IND);
    cudaEventRecord(eGemm1, s1);

    // ---- main: finish CSR ----
    scan_offsets_kernel<<<1, 128>>>(bsum, boff, rowptr, NN);
    scan_write_kernel<<<SC_NB, SC_T>>>(deg, boff, rowptr, fill, NN);
    fill_kernel<<<(E + 255) / 256, 256>>>(src, dst, fill, csrc, E);

    // ---- join, serial tail (R7 structure) ----
    cudaStreamWaitEvent(0, eGemm1, 0);
    gather128_kernel<<<warpsGrid, 256>>>((const float4*)h1, csrc, rowptr, dinv, (float4*)agg1);
    mma_gemm_kernel<OUTD, 4, 2, true><<<gemmGrid, 256>>>(agg1, w2hi, w2lo, b1, dinv, h2, NN, HID);
    gather64_kernel<<<warpsGrid, 256>>>((const float2*)h2, csrc, rowptr, dinv, b2, (float2*)out);
}

// round 10
// speedup vs baseline: 1.5909x; 1.0694x over previous
#include <cuda_runtime.h>
#include <cuda_bf16.h>
#include <cstdint>

#define NN   50000
#define IND  256
#define HID  128
#define OUTD 64
#define EMAX 800000

// scan config: small chunks for full-chip occupancy
#define SC_T     256
#define SC_I     2
#define SC_CHUNK (SC_T * SC_I)                     // 512
#define SC_NB    ((NN + SC_CHUNK - 1) / SC_CHUNK)  // 98

// -------- device scratch --------
__device__ float g_h1[NN * HID];
__device__ float g_agg1[NN * HID];
__device__ float g_h2[NN * OUTD];
__device__ float g_dinv[NN];
__device__ int   g_deg[NN];          // raw in-edge counts (no self loop)
__device__ int   g_rowptr[NN + 1];
__device__ int   g_fill[NN];
__device__ int   g_csrc[EMAX];
__device__ int   g_bsum[SC_NB];
__device__ int   g_boff[SC_NB];
__device__ __nv_bfloat16 g_w1hi[HID * IND];
__device__ __nv_bfloat16 g_w1lo[HID * IND];
__device__ __nv_bfloat16 g_w2hi[OUTD * HID];
__device__ __nv_bfloat16 g_w2lo[OUTD * HID];

// ---------------- prep: deg=0 + both weight splits in ONE launch ----------------
__global__ void prep_kernel(int* __restrict__ deg,
                            const float* __restrict__ W1, const float* __restrict__ W2,
                            __nv_bfloat16* __restrict__ T1h, __nv_bfloat16* __restrict__ T1l,
                            __nv_bfloat16* __restrict__ T2h, __nv_bfloat16* __restrict__ T2l) {
    int i = blockIdx.x * blockDim.x + threadIdx.x;
    if (i < NN) deg[i] = 0;
    const int n1 = IND * HID;
    const int n2 = HID * OUTD;
    if (i < n1) {
        int k = i / HID, n = i % HID;
        float v = W1[i];
        __nv_bfloat16 h = __float2bfloat16(v);
        T1h[(size_t)n * IND + k] = h;
        T1l[(size_t)n * IND + k] = __float2bfloat16(v - __bfloat162float(h));
    } else if (i < n1 + n2) {
        int j = i - n1;
        int k = j / OUTD, n = j % OUTD;
        float v = W2[j];
        __nv_bfloat16 h = __float2bfloat16(v);
        T2h[(size_t)n * HID + k] = h;
        T2l[(size_t)n * HID + k] = __float2bfloat16(v - __bfloat162float(h));
    }
}

__global__ void deg_count_kernel(const int* __restrict__ dst, int* __restrict__ deg, int E) {
    int i = blockIdx.x * blockDim.x + threadIdx.x;
    if (i < E) atomicAdd(&deg[dst[i]], 1);
}

// ---------------- scan chain (98 blocks, coalesced) ----------------
__global__ void scan_reduce_kernel(const int* __restrict__ deg, int* __restrict__ bsum,
                                   float* __restrict__ dinv, int n) {
    __shared__ int ws[SC_T / 32];
    int b = blockIdx.x, tid = threadIdx.x;
    int base = b * SC_CHUNK;
    int s = 0;
#pragma unroll
    for (int u = 0; u < SC_I; u++) {
        int i = base + u * SC_T + tid;
        if (i < n) {
            int c = deg[i];
            s += c;
            dinv[i] = rsqrtf((float)(c + 1));
        }
    }
#pragma unroll
    for (int d = 16; d; d >>= 1) s += __shfl_down_sync(0xffffffffu, s, d);
    if ((tid & 31) == 0) ws[tid >> 5] = s;
    __syncthreads();
    if (tid < 32) {
        int v = (tid < SC_T / 32) ? ws[tid] : 0;
#pragma unroll
        for (int d = 16; d; d >>= 1) v += __shfl_down_sync(0xffffffffu, v, d);
        if (tid == 0) bsum[b] = v;
    }
}

// 128-thread scan over SC_NB (=98) block sums
__global__ void scan_offsets_kernel(const int* __restrict__ bsum, int* __restrict__ boff,
                                    int* __restrict__ rowptr, int n) {
    __shared__ int ws[4];
    int tid = threadIdx.x;
    int lane = tid & 31, wid = tid >> 5;
    int v = (tid < SC_NB) ? bsum[tid] : 0;
    int x = v;
#pragma unroll
    for (int d = 1; d < 32; d <<= 1) {
        int y = __shfl_up_sync(0xffffffffu, x, d);
        if (lane >= d) x += y;
    }
    if (lane == 31) ws[wid] = x;
    __syncthreads();
    if (tid == 0) {
        int acc = 0;
#pragma unroll
        for (int k = 0; k < 4; k++) { int t = ws[k]; ws[k] = acc; acc += t; }
        rowptr[n] = acc;
    }
    __syncthreads();
    if (tid < SC_NB) boff[tid] = x - v + ws[wid];
}

// writes rowptr AND fill (atomic cursor copy)
__global__ void scan_write_kernel(const int* __restrict__ deg, const int* __restrict__ boff,
                                  int* __restrict__ rowptr, int* __restrict__ fill, int n) {
    __shared__ int sbuf[SC_CHUNK];
    __shared__ int ws[SC_T / 32];
    int b = blockIdx.x, tid = threadIdx.x;
    int lane = tid & 31, wid = tid >> 5;
    int base = b * SC_CHUNK;

#pragma unroll
    for (int u = 0; u < SC_I; u++) {
        int i = base + u * SC_T + tid;
        sbuf[u * SC_T + tid] = (i < n) ? deg[i] : 0;
    }
    __syncthreads();

    int v[SC_I];
    int tot = 0;
#pragma unroll
    for (int u = 0; u < SC_I; u++) {
        int d = sbuf[tid * SC_I + u];
        v[u] = tot;
        tot += d;
    }
    int x = tot;
#pragma unroll
    for (int d = 1; d < 32; d <<= 1) {
        int y = __shfl_up_sync(0xffffffffu, x, d);
        if (lane >= d) x += y;
    }
    if (lane == 31) ws[wid] = x;
    __syncthreads();
    if (wid == 0) {
        int y = (lane < SC_T / 32) ? ws[lane] : 0;
#pragma unroll
        for (int d = 1; d < 32; d <<= 1) {
            int z = __shfl_up_sync(0xffffffffu, y, d);
            if (lane >= d) y += z;
        }
        if (lane < SC_T / 32) ws[lane] = y;
    }
    __syncthreads();
    int off = boff[b] + (x - tot) + (wid ? ws[wid - 1] : 0);
#pragma unroll
    for (int u = 0; u < SC_I; u++) sbuf[tid * SC_I + u] = off + v[u];
    __syncthreads();

#pragma unroll
    for (int u = 0; u < SC_I; u++) {
        int i = base + u * SC_T + tid;
        if (i < n) {
            int r = sbuf[u * SC_T + tid];
            rowptr[i] = r;
            fill[i] = r;
        }
    }
}

__global__ void fill_kernel(const int* __restrict__ src, const int* __restrict__ dst,
                            int* __restrict__ fill, int* __restrict__ csrc, int E) {
    int i = blockIdx.x * blockDim.x + threadIdx.x;
    if (i >= E) return;
    int pos = atomicAdd(&fill[dst[i]], 1);
    csrc[pos] = src[i];
}

// ---------------- split-bf16 tensor-core GEMM ----------------
#define MMA_BF16(c, a, b) asm volatile( \
    "mma.sync.aligned.m16n8k16.row.col.f32.bf16.bf16.f32 " \
    "{%0,%1,%2,%3}, {%4,%5,%6,%7}, {%8,%9}, {%0,%1,%2,%3};" \
    : "+f"((c)[0]), "+f"((c)[1]), "+f"((c)[2]), "+f"((c)[3]) \
    : "r"((a)[0]), "r"((a)[1]), "r"((a)[2]), "r"((a)[3]), "r"((b)[0]), "r"((b)[1]))

template<int BN, int WGM, int WGN, bool FUSE>
__global__ __launch_bounds__(256, 2)
void mma_gemm_kernel(const float* __restrict__ A,
                     const __nv_bfloat16* __restrict__ BThi,
                     const __nv_bfloat16* __restrict__ BTlo,
                     const float* __restrict__ bias,
                     const float* __restrict__ rowscale,
                     float* __restrict__ C, int M, int K) {
    constexpr int BM = 128, BK = 16, BKP = 20;
    constexpr int MI = BM / (WGM * 16);
    constexpr int NI = BN / (WGN * 8);
    constexpr int NBU = BN * 8 / 256;

    __shared__ __nv_bfloat16 sAhi[2][BM][BKP], sAlo[2][BM][BKP];
    __shared__ __nv_bfloat16 sBhi[2][BN][BKP], sBlo[2][BN][BKP];

    const int tid  = threadIdx.x;
    const int m0   = blockIdx.x * BM;
    const int w    = tid >> 5, lane = tid & 31;
    const int wm   = (w / WGN) * MI * 16;
    const int wn   = (w % WGN) * NI * 8;
    const int gid  = lane >> 2, tig = lane & 3;

    float4   rA[2];
    uint32_t rBh[NBU], rBl[NBU];

    float acc[MI][NI][4];
#pragma unroll
    for (int i = 0; i < MI; i++)
#pragma unroll
        for (int j = 0; j < NI; j++) {
            acc[i][j][0] = 0.f; acc[i][j][1] = 0.f; acc[i][j][2] = 0.f; acc[i][j][3] = 0.f;
        }

    auto loadA = [&](int k0) {
#pragma unroll
        for (int u = 0; u < 2; u++) {
            int idx = tid + u * 256;
            int row = idx >> 2;
            int c4  = idx & 3;
            float4 v = make_float4(0.f, 0.f, 0.f, 0.f);
            int gm = m0 + row;
            if (gm < M) {
                v = *(const float4*)(A + (size_t)gm * K + k0 + c4 * 4);
                if (FUSE) {
                    int kk = k0 + c4 * 4;
                    v.x = fmaxf(v.x + bias[kk + 0], 0.f);
                    v.y = fmaxf(v.y + bias[kk + 1], 0.f);
                    v.z = fmaxf(v.z + bias[kk + 2], 0.f);
                    v.w = fmaxf(v.w + bias[kk + 3], 0.f);
                }
            }
            rA[u] = v;
        }
    };
    auto loadB = [&](int k0) {
#pragma unroll
        for (int u = 0; u < NBU; u++) {
            int idx = tid + u * 256;
            int n = idx >> 3;
            int c = idx & 7;
            rBh[u] = *(const uint32_t*)(BThi + (size_t)n * K + k0 + c * 2);
            rBl[u] = *(const uint32_t*)(BTlo + (size_t)n * K + k0 + c * 2);
        }
    };
    auto storeTile = [&](int buf) {
#pragma unroll
        for (int u = 0; u < 2; u++) {
            int idx = tid + u * 256;
            int row = idx >> 2;
            int c4  = idx & 3;
            float4 v = rA[u];
            __nv_bfloat162 h0 = __floats2bfloat162_rn(v.x, v.y);
            __nv_bfloat162 h1 = __floats2bfloat162_rn(v.z, v.w);
            __nv_bfloat162 l0 = __floats2bfloat162_rn(v.x - __bfloat162float(h0.x),
                                                      v.y - __bfloat162float(h0.y));
            __nv_bfloat162 l1 = __floats2bfloat162_rn(v.z - __bfloat162float(h1.x),
                                                      v.w - __bfloat162float(h1.y));
            *(__nv_bfloat162*)&sAhi[buf][row][c4 * 4]     = h0;
            *(__nv_bfloat162*)&sAhi[buf][row][c4 * 4 + 2] = h1;
            *(__nv_bfloat162*)&sAlo[buf][row][c4 * 4]     = l0;
            *(__nv_bfloat162*)&sAlo[buf][row][c4 * 4 + 2] = l1;
        }
#pragma unroll
        for (int u = 0; u < NBU; u++) {
            int idx = tid + u * 256;
            int n = idx >> 3;
            int c = idx & 7;
            *(uint32_t*)&sBhi[buf][n][c * 2] = rBh[u];
            *(uint32_t*)&sBlo[buf][n][c * 2] = rBl[u];
        }
    };

    const int nIter = K / BK;
    loadA(0); loadB(0);
    storeTile(0);
    __syncthreads();

    for (int it = 0; it < nIter; ++it) {
        if (it + 1 < nIter) { loadA((it + 1) * BK); loadB((it + 1) * BK); }
        const int p = it & 1;

        uint32_t ah[MI][4], al[MI][4];
#pragma unroll
        for (int mi = 0; mi < MI; mi++) {
            int r = wm + mi * 16 + gid;
            ah[mi][0] = *(const uint32_t*)&sAhi[p][r][2 * tig];
            ah[mi][1] = *(const uint32_t*)&sAhi[p][r + 8][2 * tig];
            ah[mi][2] = *(const uint32_t*)&sAhi[p][r][2 * tig + 8];
            ah[mi][3] = *(const uint32_t*)&sAhi[p][r + 8][2 * tig + 8];
            al[mi][0] = *(const uint32_t*)&sAlo[p][r][2 * tig];
            al[mi][1] = *(const uint32_t*)&sAlo[p][r + 8][2 * tig];
            al[mi][2] = *(const uint32_t*)&sAlo[p][r][2 * tig + 8];
            al[mi][3] = *(const uint32_t*)&sAlo[p][r + 8][2 * tig + 8];
        }
        uint32_t bh[NI][2], bl[NI][2];
#pragma unroll
        for (int ni = 0; ni < NI; ni++) {
            int n = wn + ni * 8 + gid;
            bh[ni][0] = *(const uint32_t*)&sBhi[p][n][2 * tig];
            bh[ni][1] = *(const uint32_t*)&sBhi[p][n][2 * tig + 8];
            bl[ni][0] = *(const uint32_t*)&sBlo[p][n][2 * tig];
            bl[ni][1] = *(const uint32_t*)&sBlo[p][n][2 * tig + 8];
        }
#pragma unroll
        for (int mi = 0; mi < MI; mi++)
#pragma unroll
            for (int ni = 0; ni < NI; ni++) {
                MMA_BF16(acc[mi][ni], ah[mi], bh[ni]);
                MMA_BF16(acc[mi][ni], ah[mi], bl[ni]);
                MMA_BF16(acc[mi][ni], al[mi], bh[ni]);
            }

        if (it + 1 < nIter) storeTile((it + 1) & 1);
        __syncthreads();
    }

#pragma unroll
    for (int mi = 0; mi < MI; mi++) {
        int r0 = m0 + wm + mi * 16 + gid;
        int r1 = r0 + 8;
        float s0 = (r0 < M) ? rowscale[r0] : 0.f;
        float s1 = (r1 < M) ? rowscale[r1] : 0.f;
#pragma unroll
        for (int ni = 0; ni < NI; ni++) {
            int col = wn + ni * 8 + 2 * tig;
            if (r0 < M)
                *(float2*)(C + (size_t)r0 * BN + col) =
                    make_float2(acc[mi][ni][0] * s0, acc[mi][ni][1] * s0);
            if (r1 < M)
                *(float2*)(C + (size_t)r1 * BN + col) =
                    make_float2(acc[mi][ni][2] * s1, acc[mi][ni][3] * s1);
        }
    }
}

// ---------------- CSR gather aggregation (inputs pre-scaled by dinv) ----------------
__global__ void gather128_kernel(const float4* __restrict__ hs, const int* __restrict__ csrc,
                                 const int* __restrict__ rowptr, const float* __restrict__ dinv,
                                 float4* __restrict__ out) {
    int w = (blockIdx.x * blockDim.x + threadIdx.x) >> 5;
    if (w >= NN) return;
    int lane = threadIdx.x & 31;
    int begin = rowptr[w], end = rowptr[w + 1];
    float4 a0 = __ldg(&hs[(size_t)w * 32 + lane]);
    float4 a1 = make_float4(0.f, 0.f, 0.f, 0.f);
    float4 a2 = make_float4(0.f, 0.f, 0.f, 0.f);
    float4 a3 = make_float4(0.f, 0.f, 0.f, 0.f);
    int j = begin;
    for (; j + 4 <= end; j += 4) {
        int s0 = __ldg(&csrc[j]);
        int s1 = __ldg(&csrc[j + 1]);
        int s2 = __ldg(&csrc[j + 2]);
        int s3 = __ldg(&csrc[j + 3]);
        float4 v0 = __ldg(&hs[(size_t)s0 * 32 + lane]);
        float4 v1 = __ldg(&hs[(size_t)s1 * 32 + lane]);
        float4 v2 = __ldg(&hs[(size_t)s2 * 32 + lane]);
        float4 v3 = __ldg(&hs[(size_t)s3 * 32 + lane]);
        a0.x += v0.x; a0.y += v0.y; a0.z += v0.z; a0.w += v0.w;
        a1.x += v1.x; a1.y += v1.y; a1.z += v1.z; a1.w += v1.w;
        a2.x += v2.x; a2.y += v2.y; a2.z += v2.z; a2.w += v2.w;
        a3.x += v3.x; a3.y += v3.y; a3.z += v3.z; a3.w += v3.w;
    }
    for (; j < end; ++j) {
        int s0 = __ldg(&csrc[j]);
        float4 v0 = __ldg(&hs[(size_t)s0 * 32 + lane]);
        a0.x += v0.x; a0.y += v0.y; a0.z += v0.z; a0.w += v0.w;
    }
    float dv = dinv[w];
    float4 r;
    r.x = dv * ((a0.x + a1.x) + (a2.x + a3.x));
    r.y = dv * ((a0.y + a1.y) + (a2.y + a3.y));
    r.z = dv * ((a0.z + a1.z) + (a2.z + a3.z));
    r.w = dv * ((a0.w + a1.w) + (a2.w + a3.w));
    out[(size_t)w * 32 + lane] = r;
}

__global__ void gather64_kernel(const float2* __restrict__ hs, const int* __restrict__ csrc,
                                const int* __restrict__ rowptr, const float* __restrict__ dinv,
                                const float* __restrict__ b2, float2* __restrict__ out) {
    int w = (blockIdx.x * blockDim.x + threadIdx.x) >> 5;
    if (w >= NN) return;
    int lane = threadIdx.x & 31;
    int begin = rowptr[w], end = rowptr[w + 1];
    float2 a0 = __ldg(&hs[(size_t)w * 32 + lane]);
    float2 a1 = make_float2(0.f, 0.f);
    float2 a2 = make_float2(0.f, 0.f);
    float2 a3 = make_float2(0.f, 0.f);
    int j = begin;
    for (; j + 4 <= end; j += 4) {
        int s0 = __ldg(&csrc[j]);
        int s1 = __ldg(&csrc[j + 1]);
        int s2 = __ldg(&csrc[j + 2]);
        int s3 = __ldg(&csrc[j + 3]);
        float2 v0 = __ldg(&hs[(size_t)s0 * 32 + lane]);
        float2 v1 = __ldg(&hs[(size_t)s1 * 32 + lane]);
        float2 v2 = __ldg(&hs[(size_t)s2 * 32 + lane]);
        float2 v3 = __ldg(&hs[(size_t)s3 * 32 + lane]);
        a0.x += v0.x; a0.y += v0.y;
        a1.x += v1.x; a1.y += v1.y;
        a2.x += v2.x; a2.y += v2.y;
        a3.x += v3.x; a3.y += v3.y;
    }
    for (; j < end; ++j) {
        int s0 = __ldg(&csrc[j]);
        float2 v0 = __ldg(&hs[(size_t)s0 * 32 + lane]);
        a0.x += v0.x; a0.y += v0.y;
    }
    float dv = dinv[w];
    float2 r;
    r.x = dv * ((a0.x + a1.x) + (a2.x + a3.x)) + b2[lane * 2 + 0];
    r.y = dv * ((a0.y + a1.y) + (a2.y + a3.y)) + b2[lane * 2 + 1];
    out[(size_t)w * 32 + lane] = r;
}

// ---------------- launch (R7 topology) ----------------
extern "C" void kernel_launch(void* const* d_in, const int* in_sizes, int n_in,
                              void* d_out, int out_size) {
    const float* x   = (const float*)d_in[0];
    const int*   ei  = (const int*)d_in[1];   // int32 (JAX x64 disabled)
    const float* W1  = (const float*)d_in[2];
    const float* b1  = (const float*)d_in[3];
    const float* W2  = (const float*)d_in[4];
    const float* b2  = (const float*)d_in[5];
    float*       out = (float*)d_out;

    const int E = in_sizes[1] / 2;
    const int* src = ei;
    const int* dst = ei + E;

    void* p;
    cudaGetSymbolAddress(&p, g_h1);     float* h1     = (float*)p;
    cudaGetSymbolAddress(&p, g_agg1);   float* agg1   = (float*)p;
    cudaGetSymbolAddress(&p, g_h2);     float* h2     = (float*)p;
    cudaGetSymbolAddress(&p, g_dinv);   float* dinv   = (float*)p;
    cudaGetSymbolAddress(&p, g_deg);    int*   deg    = (int*)p;
    cudaGetSymbolAddress(&p, g_rowptr); int*   rowptr = (int*)p;
    cudaGetSymbolAddress(&p, g_fill);   int*   fill   = (int*)p;
    cudaGetSymbolAddress(&p, g_csrc);   int*   csrc   = (int*)p;
    cudaGetSymbolAddress(&p, g_bsum);   int*   bsum   = (int*)p;
    cudaGetSymbolAddress(&p, g_boff);   int*   boff   = (int*)p;
    cudaGetSymbolAddress(&p, g_w1hi);   __nv_bfloat16* w1hi = (__nv_bfloat16*)p;
    cudaGetSymbolAddress(&p, g_w1lo);   __nv_bfloat16* w1lo = (__nv_bfloat16*)p;
    cudaGetSymbolAddress(&p, g_w2hi);   __nv_bfloat16* w2hi = (__nv_bfloat16*)p;
    cudaGetSymbolAddress(&p, g_w2lo);   __nv_bfloat16* w2lo = (__nv_bfloat16*)p;

    static cudaStream_t s1 = nullptr;
    static cudaEvent_t  eDinv = nullptr, eGemm1 = nullptr;
    if (!s1) {
        cudaStreamCreateWithFlags(&s1, cudaStreamNonBlocking);
        cudaEventCreateWithFlags(&eDinv,  cudaEventDisableTiming);
        cudaEventCreateWithFlags(&eGemm1, cudaEventDisableTiming);
    }

    const int warpsGrid = (NN * 32 + 255) / 256;
    const int gemmGrid  = (NN + 127) / 128;

    // ---- main: prep (deg=0 + wsplit) -> degree counts -> dinv/bsum ----
    prep_kernel<<<(NN + 255) / 256, 256>>>(deg, W1, W2, w1hi, w1lo, w2hi, w2lo);
    deg_count_kernel<<<(E + 255) / 256, 256>>>(dst, deg, E);
    scan_reduce_kernel<<<SC_NB, SC_T>>>(deg, bsum, dinv, NN);
    cudaEventRecord(eDinv, 0);

    // ---- s1: GEMM1 overlaps CSR build ----
    cudaStreamWaitEvent(s1, eDinv, 0);
    mma_gemm_kernel<HID, 2, 4, false><<<gemmGrid, 256, 0, s1>>>(
        x, w1hi, w1lo, nullptr, dinv, h1, NN, IND);
    cudaEventRecord(eGemm1, s1);

    // ---- main: finish CSR ----
    scan_offsets_kernel<<<1, 128>>>(bsum, boff, rowptr, NN);
    scan_write_kernel<<<SC_NB, SC_T>>>(deg, boff, rowptr, fill, NN);
    fill_kernel<<<(E + 255) / 256, 256>>>(src, dst, fill, csrc, E);

    // ---- join, serial tail ----
    cudaStreamWaitEvent(0, eGemm1, 0);
    gather128_kernel<<<warpsGrid, 256>>>((const float4*)h1, csrc, rowptr, dinv, (float4*)agg1);
    mma_gemm_kernel<OUTD, 4, 2, true><<<gemmGrid, 256>>>(agg1, w2hi, w2lo, b1, dinv, h2, NN, HID);
    gather64_kernel<<<warpsGrid, 256>>>((const float2*)h2, csrc, rowptr, dinv, b2, (float2*)out);
}

// round 11
// speedup vs baseline: 1.7103x; 1.0751x over previous
#include <cuda_runtime.h>
#include <cuda_bf16.h>
#include <cstdint>

#define NN   50000
#define IND  256
#define HID  128
#define OUTD 64
#define EMAX 800000

// scan config
#define SC_T     256
#define SC_I     2
#define SC_CHUNK (SC_T * SC_I)                     // 512
#define SC_NB    ((NN + SC_CHUNK - 1) / SC_CHUNK)  // 98

// -------- device scratch --------
__device__ float g_h1[NN * HID];
__device__ float g_agg1[NN * HID];
__device__ float g_h2[NN * OUTD];
__device__ float g_dinv[NN];
__device__ int   g_deg[NN];
__device__ int   g_rowptr[NN + 1];
__device__ int   g_fill[NN];
__device__ int   g_csrc[EMAX];
__device__ int   g_bsum[SC_NB];
__device__ int   g_boff[SC_NB];
__device__ __nv_bfloat16 g_w1hi[HID * IND];
__device__ __nv_bfloat16 g_w1lo[HID * IND];
__device__ __nv_bfloat16 g_w2hi[OUTD * HID];
__device__ __nv_bfloat16 g_w2lo[OUTD * HID];

// ---------------- prep: deg=0 + both weight splits ----------------
__global__ void prep_kernel(int* __restrict__ deg,
                            const float* __restrict__ W1, const float* __restrict__ W2,
                            __nv_bfloat16* __restrict__ T1h, __nv_bfloat16* __restrict__ T1l,
                            __nv_bfloat16* __restrict__ T2h, __nv_bfloat16* __restrict__ T2l) {
    int i = blockIdx.x * blockDim.x + threadIdx.x;
    if (i < NN) deg[i] = 0;
    const int n1 = IND * HID;
    const int n2 = HID * OUTD;
    if (i < n1) {
        int k = i / HID, n = i % HID;
        float v = W1[i];
        __nv_bfloat16 h = __float2bfloat16(v);
        T1h[(size_t)n * IND + k] = h;
        T1l[(size_t)n * IND + k] = __float2bfloat16(v - __bfloat162float(h));
    } else if (i < n1 + n2) {
        int j = i - n1;
        int k = j / OUTD, n = j % OUTD;
        float v = W2[j];
        __nv_bfloat16 h = __float2bfloat16(v);
        T2h[(size_t)n * HID + k] = h;
        T2l[(size_t)n * HID + k] = __float2bfloat16(v - __bfloat162float(h));
    }
}

__global__ void deg_count_kernel(const int* __restrict__ dst, int* __restrict__ deg, int E) {
    int i = blockIdx.x * blockDim.x + threadIdx.x;
    if (i < E) atomicAdd(&deg[dst[i]], 1);
}

// ---------------- scan chain ----------------
__global__ void scan_reduce_kernel(const int* __restrict__ deg, int* __restrict__ bsum,
                                   float* __restrict__ dinv, int n) {
    __shared__ int ws[SC_T / 32];
    int b = blockIdx.x, tid = threadIdx.x;
    int base = b * SC_CHUNK;
    int s = 0;
#pragma unroll
    for (int u = 0; u < SC_I; u++) {
        int i = base + u * SC_T + tid;
        if (i < n) {
            int c = deg[i];
            s += c;
            dinv[i] = rsqrtf((float)(c + 1));
        }
    }
#pragma unroll
    for (int d = 16; d; d >>= 1) s += __shfl_down_sync(0xffffffffu, s, d);
    if ((tid & 31) == 0) ws[tid >> 5] = s;
    __syncthreads();
    if (tid < 32) {
        int v = (tid < SC_T / 32) ? ws[tid] : 0;
#pragma unroll
        for (int d = 16; d; d >>= 1) v += __shfl_down_sync(0xffffffffu, v, d);
        if (tid == 0) bsum[b] = v;
    }
}

__global__ void scan_offsets_kernel(const int* __restrict__ bsum, int* __restrict__ boff,
                                    int* __restrict__ rowptr, int n) {
    __shared__ int ws[4];
    int tid = threadIdx.x;
    int lane = tid & 31, wid = tid >> 5;
    int v = (tid < SC_NB) ? bsum[tid] : 0;
    int x = v;
#pragma unroll
    for (int d = 1; d < 32; d <<= 1) {
        int y = __shfl_up_sync(0xffffffffu, x, d);
        if (lane >= d) x += y;
    }
    if (lane == 31) ws[wid] = x;
    __syncthreads();
    if (tid == 0) {
        int acc = 0;
#pragma unroll
        for (int k = 0; k < 4; k++) { int t = ws[k]; ws[k] = acc; acc += t; }
        rowptr[n] = acc;
    }
    __syncthreads();
    if (tid < SC_NB) boff[tid] = x - v + ws[wid];
}

__global__ void scan_write_kernel(const int* __restrict__ deg, const int* __restrict__ boff,
                                  int* __restrict__ rowptr, int* __restrict__ fill, int n) {
    __shared__ int sbuf[SC_CHUNK];
    __shared__ int ws[SC_T / 32];
    int b = blockIdx.x, tid = threadIdx.x;
    int lane = tid & 31, wid = tid >> 5;
    int base = b * SC_CHUNK;

#pragma unroll
    for (int u = 0; u < SC_I; u++) {
        int i = base + u * SC_T + tid;
        sbuf[u * SC_T + tid] = (i < n) ? deg[i] : 0;
    }
    __syncthreads();

    int v[SC_I];
    int tot = 0;
#pragma unroll
    for (int u = 0; u < SC_I; u++) {
        int d = sbuf[tid * SC_I + u];
        v[u] = tot;
        tot += d;
    }
    int x = tot;
#pragma unroll
    for (int d = 1; d < 32; d <<= 1) {
        int y = __shfl_up_sync(0xffffffffu, x, d);
        if (lane >= d) x += y;
    }
    if (lane == 31) ws[wid] = x;
    __syncthreads();
    if (wid == 0) {
        int y = (lane < SC_T / 32) ? ws[lane] : 0;
#pragma unroll
        for (int d = 1; d < 32; d <<= 1) {
            int z = __shfl_up_sync(0xffffffffu, y, d);
            if (lane >= d) y += z;
        }
        if (lane < SC_T / 32) ws[lane] = y;
    }
    __syncthreads();
    int off = boff[b] + (x - tot) + (wid ? ws[wid - 1] : 0);
#pragma unroll
    for (int u = 0; u < SC_I; u++) sbuf[tid * SC_I + u] = off + v[u];
    __syncthreads();

#pragma unroll
    for (int u = 0; u < SC_I; u++) {
        int i = base + u * SC_T + tid;
        if (i < n) {
            int r = sbuf[u * SC_T + tid];
            rowptr[i] = r;
            fill[i] = r;
        }
    }
}

__global__ void fill_kernel(const int* __restrict__ src, const int* __restrict__ dst,
                            int* __restrict__ fill, int* __restrict__ csrc, int E) {
    int i = blockIdx.x * blockDim.x + threadIdx.x;
    if (i >= E) return;
    int pos = atomicAdd(&fill[dst[i]], 1);
    csrc[pos] = src[i];
}

// ---------------- split-bf16 tensor-core GEMM with ldmatrix ----------------
#define MMA_BF16(c, a, b) asm volatile( \
    "mma.sync.aligned.m16n8k16.row.col.f32.bf16.bf16.f32 " \
    "{%0,%1,%2,%3}, {%4,%5,%6,%7}, {%8,%9}, {%0,%1,%2,%3};" \
    : "+f"((c)[0]), "+f"((c)[1]), "+f"((c)[2]), "+f"((c)[3]) \
    : "r"((a)[0]), "r"((a)[1]), "r"((a)[2]), "r"((a)[3]), "r"((b)[0]), "r"((b)[1]))

__device__ __forceinline__ void ldsm_x4(uint32_t* r, uint32_t addr) {
    asm volatile("ldmatrix.sync.aligned.m8n8.x4.shared.b16 {%0,%1,%2,%3}, [%4];"
                 : "=r"(r[0]), "=r"(r[1]), "=r"(r[2]), "=r"(r[3]) : "r"(addr));
}

template<int BN, int WGM, int WGN, bool FUSE>
__global__ __launch_bounds__(256, 2)
void mma_gemm_kernel(const float* __restrict__ A,
                     const __nv_bfloat16* __restrict__ BThi,
                     const __nv_bfloat16* __restrict__ BTlo,
                     const float* __restrict__ bias,
                     const float* __restrict__ rowscale,
                     float* __restrict__ C, int M, int K) {
    constexpr int BM = 128, BK = 16, BKP = 24;      // 48B row stride: 16B-aligned for ldmatrix
    constexpr int MI = BM / (WGM * 16);
    constexpr int NI = BN / (WGN * 8);
    constexpr int NBU = BN * 8 / 256;

    __shared__ __align__(16) __nv_bfloat16 sAhi[2][BM][BKP], sAlo[2][BM][BKP];
    __shared__ __align__(16) __nv_bfloat16 sBhi[2][BN][BKP], sBlo[2][BN][BKP];

    const int tid  = threadIdx.x;
    const int m0   = blockIdx.x * BM;
    const int w    = tid >> 5, lane = tid & 31;
    const int wm   = (w / WGN) * MI * 16;
    const int wn   = (w % WGN) * NI * 8;
    const int gid  = lane >> 2, tig = lane & 3;

    // ldmatrix lane->address mapping (element row / byte col within fragment)
    const int aRow  = lane & 15;                 // rows of 16x16 A fragment
    const int aColB = (lane >> 4) * 16;          // 0 or 16 bytes (k 0-7 / 8-15)
    const int bRow  = (lane & 7) + ((lane >> 4) << 3);  // two n-tiles per x4
    const int bColB = ((lane >> 3) & 1) * 16;

    const uint32_t uAhi = (uint32_t)__cvta_generic_to_shared(&sAhi[0][0][0]);
    const uint32_t uAlo = (uint32_t)__cvta_generic_to_shared(&sAlo[0][0][0]);
    const uint32_t uBhi = (uint32_t)__cvta_generic_to_shared(&sBhi[0][0][0]);
    const uint32_t uBlo = (uint32_t)__cvta_generic_to_shared(&sBlo[0][0][0]);
    constexpr int ASTG = BM * BKP * 2;           // bytes per A stage
    constexpr int BSTG = BN * BKP * 2;

    float4   rA[2];
    uint32_t rBh[NBU], rBl[NBU];

    float acc[MI][NI][4];
#pragma unroll
    for (int i = 0; i < MI; i++)
#pragma unroll
        for (int j = 0; j < NI; j++) {
            acc[i][j][0] = 0.f; acc[i][j][1] = 0.f; acc[i][j][2] = 0.f; acc[i][j][3] = 0.f;
        }

    auto loadA = [&](int k0) {
#pragma unroll
        for (int u = 0; u < 2; u++) {
            int idx = tid + u * 256;
            int row = idx >> 2;
            int c4  = idx & 3;
            float4 v = make_float4(0.f, 0.f, 0.f, 0.f);
            int gm = m0 + row;
            if (gm < M) {
                v = *(const float4*)(A + (size_t)gm * K + k0 + c4 * 4);
                if (FUSE) {
                    int kk = k0 + c4 * 4;
                    v.x = fmaxf(v.x + bias[kk + 0], 0.f);
                    v.y = fmaxf(v.y + bias[kk + 1], 0.f);
                    v.z = fmaxf(v.z + bias[kk + 2], 0.f);
                    v.w = fmaxf(v.w + bias[kk + 3], 0.f);
                }
            }
            rA[u] = v;
        }
    };
    auto loadB = [&](int k0) {
#pragma unroll
        for (int u = 0; u < NBU; u++) {
            int idx = tid + u * 256;
            int n = idx >> 3;
            int c = idx & 7;
            rBh[u] = *(const uint32_t*)(BThi + (size_t)n * K + k0 + c * 2);
            rBl[u] = *(const uint32_t*)(BTlo + (size_t)n * K + k0 + c * 2);
        }
    };
    auto storeTile = [&](int buf) {
#pragma unroll
        for (int u = 0; u < 2; u++) {
            int idx = tid + u * 256;
            int row = idx >> 2;
            int c4  = idx & 3;
            float4 v = rA[u];
            __nv_bfloat162 h0 = __floats2bfloat162_rn(v.x, v.y);
            __nv_bfloat162 h1 = __floats2bfloat162_rn(v.z, v.w);
            __nv_bfloat162 l0 = __floats2bfloat162_rn(v.x - __bfloat162float(h0.x),
                                                      v.y - __bfloat162float(h0.y));
            __nv_bfloat162 l1 = __floats2bfloat162_rn(v.z - __bfloat162float(h1.x),
                                                      v.w - __bfloat162float(h1.y));
            uint2 hw = make_uint2(*(uint32_t*)&h0, *(uint32_t*)&h1);
            uint2 lw = make_uint2(*(uint32_t*)&l0, *(uint32_t*)&l1);
            *(uint2*)&sAhi[buf][row][c4 * 4] = hw;
            *(uint2*)&sAlo[buf][row][c4 * 4] = lw;
        }
#pragma unroll
        for (int u = 0; u < NBU; u++) {
            int idx = tid + u * 256;
            int n = idx >> 3;
            int c = idx & 7;
            *(uint32_t*)&sBhi[buf][n][c * 2] = rBh[u];
            *(uint32_t*)&sBlo[buf][n][c * 2] = rBl[u];
        }
    };

    const int nIter = K / BK;
    loadA(0); loadB(0);
    storeTile(0);
    __syncthreads();

    for (int it = 0; it < nIter; ++it) {
        if (it + 1 < nIter) { loadA((it + 1) * BK); loadB((it + 1) * BK); }
        const int p = it & 1;

        uint32_t ah[MI][4], al[MI][4];
        {
            uint32_t aBase = p * ASTG + (wm + aRow) * (BKP * 2) + aColB;
#pragma unroll
            for (int mi = 0; mi < MI; mi++) {
                ldsm_x4(ah[mi], uAhi + aBase + mi * 16 * (BKP * 2));
                ldsm_x4(al[mi], uAlo + aBase + mi * 16 * (BKP * 2));
            }
        }
        uint32_t bh[NI][2], bl[NI][2];
        {
            uint32_t bBase = p * BSTG + (wn + bRow) * (BKP * 2) + bColB;
#pragma unroll
            for (int q = 0; q < NI / 2; q++) {
                ldsm_x4(&bh[2 * q][0], uBhi + bBase + q * 16 * (BKP * 2));
                ldsm_x4(&bl[2 * q][0], uBlo + bBase + q * 16 * (BKP * 2));
            }
        }
#pragma unroll
        for (int mi = 0; mi < MI; mi++)
#pragma unroll
            for (int ni = 0; ni < NI; ni++) {
                MMA_BF16(acc[mi][ni], ah[mi], bh[ni]);
                MMA_BF16(acc[mi][ni], ah[mi], bl[ni]);
                MMA_BF16(acc[mi][ni], al[mi], bh[ni]);
            }

        if (it + 1 < nIter) storeTile((it + 1) & 1);
        __syncthreads();
    }

#pragma unroll
    for (int mi = 0; mi < MI; mi++) {
        int r0 = m0 + wm + mi * 16 + gid;
        int r1 = r0 + 8;
        float s0 = (r0 < M) ? rowscale[r0] : 0.f;
        float s1 = (r1 < M) ? rowscale[r1] : 0.f;
#pragma unroll
        for (int ni = 0; ni < NI; ni++) {
            int col = wn + ni * 8 + 2 * tig;
            if (r0 < M)
                *(float2*)(C + (size_t)r0 * BN + col) =
                    make_float2(acc[mi][ni][0] * s0, acc[mi][ni][1] * s0);
            if (r1 < M)
                *(float2*)(C + (size_t)r1 * BN + col) =
                    make_float2(acc[mi][ni][2] * s1, acc[mi][ni][3] * s1);
        }
    }
}

// ---------------- CSR gather aggregation (inputs pre-scaled by dinv) ----------------
__global__ void gather128_kernel(const float4* __restrict__ hs, const int* __restrict__ csrc,
                                 const int* __restrict__ rowptr, const float* __restrict__ dinv,
                                 float4* __restrict__ out) {
    int w = (blockIdx.x * blockDim.x + threadIdx.x) >> 5;
    if (w >= NN) return;
    int lane = threadIdx.x & 31;
    int begin = rowptr[w], end = rowptr[w + 1];
    float4 a0 = __ldg(&hs[(size_t)w * 32 + lane]);
    float4 a1 = make_float4(0.f, 0.f, 0.f, 0.f);
    float4 a2 = make_float4(0.f, 0.f, 0.f, 0.f);
    float4 a3 = make_float4(0.f, 0.f, 0.f, 0.f);
    int j = begin;
    for (; j + 4 <= end; j += 4) {
        int s0 = __ldg(&csrc[j]);
        int s1 = __ldg(&csrc[j + 1]);
        int s2 = __ldg(&csrc[j + 2]);
        int s3 = __ldg(&csrc[j + 3]);
        float4 v0 = __ldg(&hs[(size_t)s0 * 32 + lane]);
        float4 v1 = __ldg(&hs[(size_t)s1 * 32 + lane]);
        float4 v2 = __ldg(&hs[(size_t)s2 * 32 + lane]);
        float4 v3 = __ldg(&hs[(size_t)s3 * 32 + lane]);
        a0.x += v0.x; a0.y += v0.y; a0.z += v0.z; a0.w += v0.w;
        a1.x += v1.x; a1.y += v1.y; a1.z += v1.z; a1.w += v1.w;
        a2.x += v2.x; a2.y += v2.y; a2.z += v2.z; a2.w += v2.w;
        a3.x += v3.x; a3.y += v3.y; a3.z += v3.z; a3.w += v3.w;
    }
    for (; j < end; ++j) {
        int s0 = __ldg(&csrc[j]);
        float4 v0 = __ldg(&hs[(size_t)s0 * 32 + lane]);
        a0.x += v0.x; a0.y += v0.y; a0.z += v0.z; a0.w += v0.w;
    }
    float dv = dinv[w];
    float4 r;
    r.x = dv * ((a0.x + a1.x) + (a2.x + a3.x));
    r.y = dv * ((a0.y + a1.y) + (a2.y + a3.y));
    r.z = dv * ((a0.z + a1.z) + (a2.z + a3.z));
    r.w = dv * ((a0.w + a1.w) + (a2.w + a3.w));
    out[(size_t)w * 32 + lane] = r;
}

__global__ void gather64_kernel(const float2* __restrict__ hs, const int* __restrict__ csrc,
                                const int* __restrict__ rowptr, const float* __restrict__ dinv,
                                const float* __restrict__ b2, float2* __restrict__ out) {
    int w = (blockIdx.x * blockDim.x + threadIdx.x) >> 5;
    if (w >= NN) return;
    int lane = threadIdx.x & 31;
    int begin = rowptr[w], end = rowptr[w + 1];
    float2 a0 = __ldg(&hs[(size_t)w * 32 + lane]);
    float2 a1 = make_float2(0.f, 0.f);
    float2 a2 = make_float2(0.f, 0.f);
    float2 a3 = make_float2(0.f, 0.f);
    int j = begin;
    for (; j + 4 <= end; j += 4) {
        int s0 = __ldg(&csrc[j]);
        int s1 = __ldg(&csrc[j + 1]);
        int s2 = __ldg(&csrc[j + 2]);
        int s3 = __ldg(&csrc[j + 3]);
        float2 v0 = __ldg(&hs[(size_t)s0 * 32 + lane]);
        float2 v1 = __ldg(&hs[(size_t)s1 * 32 + lane]);
        float2 v2 = __ldg(&hs[(size_t)s2 * 32 + lane]);
        float2 v3 = __ldg(&hs[(size_t)s3 * 32 + lane]);
        a0.x += v0.x; a0.y += v0.y;
        a1.x += v1.x; a1.y += v1.y;
        a2.x += v2.x; a2.y += v2.y;
        a3.x += v3.x; a3.y += v3.y;
    }
    for (; j < end; ++j) {
        int s0 = __ldg(&csrc[j]);
        float2 v0 = __ldg(&hs[(size_t)s0 * 32 + lane]);
        a0.x += v0.x; a0.y += v0.y;
    }
    float dv = dinv[w];
    float2 r;
    r.x = dv * ((a0.x + a1.x) + (a2.x + a3.x)) + b2[lane * 2 + 0];
    r.y = dv * ((a0.y + a1.y) + (a2.y + a3.y)) + b2[lane * 2 + 1];
    out[(size_t)w * 32 + lane] = r;
}

// ---------------- launch ----------------
extern "C" void kernel_launch(void* const* d_in, const int* in_sizes, int n_in,
                              void* d_out, int out_size) {
    const float* x   = (const float*)d_in[0];
    const int*   ei  = (const int*)d_in[1];   // int32 (JAX x64 disabled)
    const float* W1  = (const float*)d_in[2];
    const float* b1  = (const float*)d_in[3];
    const float* W2  = (const float*)d_in[4];
    const float* b2  = (const float*)d_in[5];
    float*       out = (float*)d_out;

    const int E = in_sizes[1] / 2;
    const int* src = ei;
    const int* dst = ei + E;

    void* p;
    cudaGetSymbolAddress(&p, g_h1);     float* h1     = (float*)p;
    cudaGetSymbolAddress(&p, g_agg1);   float* agg1   = (float*)p;
    cudaGetSymbolAddress(&p, g_h2);     float* h2     = (float*)p;
    cudaGetSymbolAddress(&p, g_dinv);   float* dinv   = (float*)p;
    cudaGetSymbolAddress(&p, g_deg);    int*   deg    = (int*)p;
    cudaGetSymbolAddress(&p, g_rowptr); int*   rowptr = (int*)p;
    cudaGetSymbolAddress(&p, g_fill);   int*   fill   = (int*)p;
    cudaGetSymbolAddress(&p, g_csrc);   int*   csrc   = (int*)p;
    cudaGetSymbolAddress(&p, g_bsum);   int*   bsum   = (int*)p;
    cudaGetSymbolAddress(&p, g_boff);   int*   boff   = (int*)p;
    cudaGetSymbolAddress(&p, g_w1hi);   __nv_bfloat16* w1hi = (__nv_bfloat16*)p;
    cudaGetSymbolAddress(&p, g_w1lo);   __nv_bfloat16* w1lo = (__nv_bfloat16*)p;
    cudaGetSymbolAddress(&p, g_w2hi);   __nv_bfloat16* w2hi = (__nv_bfloat16*)p;
    cudaGetSymbolAddress(&p, g_w2lo);   __nv_bfloat16* w2lo = (__nv_bfloat16*)p;

    static cudaStream_t s1 = nullptr;
    static cudaEvent_t  eDinv = nullptr, eGemm1 = nullptr;
    if (!s1) {
        cudaStreamCreateWithFlags(&s1, cudaStreamNonBlocking);
        cudaEventCreateWithFlags(&eDinv,  cudaEventDisableTiming);
        cudaEventCreateWithFlags(&eGemm1, cudaEventDisableTiming);
    }

    const int warpsGrid = (NN * 32 + 255) / 256;
    const int gemmGrid  = (NN + 127) / 128;

    // ---- main: prep -> degree counts -> dinv/bsum ----
    prep_kernel<<<(NN + 255) / 256, 256>>>(deg, W1, W2, w1hi, w1lo, w2hi, w2lo);
    deg_count_kernel<<<(E + 255) / 256, 256>>>(dst, deg, E);
    scan_reduce_kernel<<<SC_NB, SC_T>>>(deg, bsum, dinv, NN);
    cudaEventRecord(eDinv, 0);

    // ---- s1: GEMM1 overlaps CSR build ----
    cudaStreamWaitEvent(s1, eDinv, 0);
    mma_gemm_kernel<HID, 2, 4, false><<<gemmGrid, 256, 0, s1>>>(
        x, w1hi, w1lo, nullptr, dinv, h1, NN, IND);
    cudaEventRecord(eGemm1, s1);

    // ---- main: finish CSR ----
    scan_offsets_kernel<<<1, 128>>>(bsum, boff, rowptr, NN);
    scan_write_kernel<<<SC_NB, SC_T>>>(deg, boff, rowptr, fill, NN);
    fill_kernel<<<(E + 255) / 256, 256>>>(src, dst, fill, csrc, E);

    // ---- join, serial tail ----
    cudaStreamWaitEvent(0, eGemm1, 0);
    gather128_kernel<<<warpsGrid, 256>>>((const float4*)h1, csrc, rowptr, dinv, (float4*)agg1);
    mma_gemm_kernel<OUTD, 4, 2, true><<<gemmGrid, 256>>>(agg1, w2hi, w2lo, b1, dinv, h2, NN, HID);
    gather64_kernel<<<warpsGrid, 256>>>((const float2*)h2, csrc, rowptr, dinv, b2, (float2*)out);
}

// round 12
// speedup vs baseline: 1.7149x; 1.0027x over previous
#include <cuda_runtime.h>
#include <cuda_bf16.h>
#include <cstdint>

#define NN   50000
#define IND  256
#define HID  128
#define OUTD 64
#define EMAX 800000

// scan config
#define SC_T     256
#define SC_I     2
#define SC_CHUNK (SC_T * SC_I)                     // 512
#define SC_NB    ((NN + SC_CHUNK - 1) / SC_CHUNK)  // 98

// -------- device scratch --------
__device__ float g_h1[NN * HID];     // RAW x@W1 (unscaled)
__device__ float g_agg1[NN * HID];
__device__ float g_h2[NN * OUTD];    // dinv-scaled relu(agg1+b1)@W2
__device__ float g_dinv[NN];
__device__ int   g_deg[NN];
__device__ int   g_rowptr[NN + 1];
__device__ int   g_fill[NN];
__device__ int   g_csrc[EMAX];
__device__ int   g_bsum[SC_NB];
__device__ int   g_boff[SC_NB];
__device__ __nv_bfloat16 g_w1hi[HID * IND];
__device__ __nv_bfloat16 g_w1lo[HID * IND];
__device__ __nv_bfloat16 g_w2hi[OUTD * HID];
__device__ __nv_bfloat16 g_w2lo[OUTD * HID];

// ---------------- prep: deg=0 + both weight splits ----------------
__global__ void prep_kernel(int* __restrict__ deg,
                            const float* __restrict__ W1, const float* __restrict__ W2,
                            __nv_bfloat16* __restrict__ T1h, __nv_bfloat16* __restrict__ T1l,
                            __nv_bfloat16* __restrict__ T2h, __nv_bfloat16* __restrict__ T2l) {
    int i = blockIdx.x * blockDim.x + threadIdx.x;
    if (i < NN) deg[i] = 0;
    const int n1 = IND * HID;
    const int n2 = HID * OUTD;
    if (i < n1) {
        int k = i / HID, n = i % HID;
        float v = W1[i];
        __nv_bfloat16 h = __float2bfloat16(v);
        T1h[(size_t)n * IND + k] = h;
        T1l[(size_t)n * IND + k] = __float2bfloat16(v - __bfloat162float(h));
    } else if (i < n1 + n2) {
        int j = i - n1;
        int k = j / OUTD, n = j % OUTD;
        float v = W2[j];
        __nv_bfloat16 h = __float2bfloat16(v);
        T2h[(size_t)n * HID + k] = h;
        T2l[(size_t)n * HID + k] = __float2bfloat16(v - __bfloat162float(h));
    }
}

__global__ void deg_count_kernel(const int* __restrict__ dst, int* __restrict__ deg, int E) {
    int i = blockIdx.x * blockDim.x + threadIdx.x;
    if (i < E) atomicAdd(&deg[dst[i]], 1);
}

// ---------------- scan chain ----------------
__global__ void scan_reduce_kernel(const int* __restrict__ deg, int* __restrict__ bsum,
                                   float* __restrict__ dinv, int n) {
    __shared__ int ws[SC_T / 32];
    int b = blockIdx.x, tid = threadIdx.x;
    int base = b * SC_CHUNK;
    int s = 0;
#pragma unroll
    for (int u = 0; u < SC_I; u++) {
        int i = base + u * SC_T + tid;
        if (i < n) {
            int c = deg[i];
            s += c;
            dinv[i] = rsqrtf((float)(c + 1));
        }
    }
#pragma unroll
    for (int d = 16; d; d >>= 1) s += __shfl_down_sync(0xffffffffu, s, d);
    if ((tid & 31) == 0) ws[tid >> 5] = s;
    __syncthreads();
    if (tid < 32) {
        int v = (tid < SC_T / 32) ? ws[tid] : 0;
#pragma unroll
        for (int d = 16; d; d >>= 1) v += __shfl_down_sync(0xffffffffu, v, d);
        if (tid == 0) bsum[b] = v;
    }
}

__global__ void scan_offsets_kernel(const int* __restrict__ bsum, int* __restrict__ boff,
                                    int* __restrict__ rowptr, int n) {
    __shared__ int ws[4];
    int tid = threadIdx.x;
    int lane = tid & 31, wid = tid >> 5;
    int v = (tid < SC_NB) ? bsum[tid] : 0;
    int x = v;
#pragma unroll
    for (int d = 1; d < 32; d <<= 1) {
        int y = __shfl_up_sync(0xffffffffu, x, d);
        if (lane >= d) x += y;
    }
    if (lane == 31) ws[wid] = x;
    __syncthreads();
    if (tid == 0) {
        int acc = 0;
#pragma unroll
        for (int k = 0; k < 4; k++) { int t = ws[k]; ws[k] = acc; acc += t; }
        rowptr[n] = acc;
    }
    __syncthreads();
    if (tid < SC_NB) boff[tid] = x - v + ws[wid];
}

__global__ void scan_write_kernel(const int* __restrict__ deg, const int* __restrict__ boff,
                                  int* __restrict__ rowptr, int* __restrict__ fill, int n) {
    __shared__ int sbuf[SC_CHUNK];
    __shared__ int ws[SC_T / 32];
    int b = blockIdx.x, tid = threadIdx.x;
    int lane = tid & 31, wid = tid >> 5;
    int base = b * SC_CHUNK;

#pragma unroll
    for (int u = 0; u < SC_I; u++) {
        int i = base + u * SC_T + tid;
        sbuf[u * SC_T + tid] = (i < n) ? deg[i] : 0;
    }
    __syncthreads();

    int v[SC_I];
    int tot = 0;
#pragma unroll
    for (int u = 0; u < SC_I; u++) {
        int d = sbuf[tid * SC_I + u];
        v[u] = tot;
        tot += d;
    }
    int x = tot;
#pragma unroll
    for (int d = 1; d < 32; d <<= 1) {
        int y = __shfl_up_sync(0xffffffffu, x, d);
        if (lane >= d) x += y;
    }
    if (lane == 31) ws[wid] = x;
    __syncthreads();
    if (wid == 0) {
        int y = (lane < SC_T / 32) ? ws[lane] : 0;
#pragma unroll
        for (int d = 1; d < 32; d <<= 1) {
            int z = __shfl_up_sync(0xffffffffu, y, d);
            if (lane >= d) y += z;
        }
        if (lane < SC_T / 32) ws[lane] = y;
    }
    __syncthreads();
    int off = boff[b] + (x - tot) + (wid ? ws[wid - 1] : 0);
#pragma unroll
    for (int u = 0; u < SC_I; u++) sbuf[tid * SC_I + u] = off + v[u];
    __syncthreads();

#pragma unroll
    for (int u = 0; u < SC_I; u++) {
        int i = base + u * SC_T + tid;
        if (i < n) {
            int r = sbuf[u * SC_T + tid];
            rowptr[i] = r;
            fill[i] = r;
        }
    }
}

__global__ void fill_kernel(const int* __restrict__ src, const int* __restrict__ dst,
                            int* __restrict__ fill, int* __restrict__ csrc, int E) {
    int i = blockIdx.x * blockDim.x + threadIdx.x;
    if (i >= E) return;
    int pos = atomicAdd(&fill[dst[i]], 1);
    csrc[pos] = src[i];
}

// ---------------- split-bf16 tensor-core GEMM with ldmatrix ----------------
#define MMA_BF16(c, a, b) asm volatile( \
    "mma.sync.aligned.m16n8k16.row.col.f32.bf16.bf16.f32 " \
    "{%0,%1,%2,%3}, {%4,%5,%6,%7}, {%8,%9}, {%0,%1,%2,%3};" \
    : "+f"((c)[0]), "+f"((c)[1]), "+f"((c)[2]), "+f"((c)[3]) \
    : "r"((a)[0]), "r"((a)[1]), "r"((a)[2]), "r"((a)[3]), "r"((b)[0]), "r"((b)[1]))

__device__ __forceinline__ void ldsm_x4(uint32_t* r, uint32_t addr) {
    asm volatile("ldmatrix.sync.aligned.m8n8.x4.shared.b16 {%0,%1,%2,%3}, [%4];"
                 : "=r"(r[0]), "=r"(r[1]), "=r"(r[2]), "=r"(r[3]) : "r"(addr));
}

template<int BN, int WGM, int WGN, bool FUSE, bool SCALE>
__global__ __launch_bounds__(256, 2)
void mma_gemm_kernel(const float* __restrict__ A,
                     const __nv_bfloat16* __restrict__ BThi,
                     const __nv_bfloat16* __restrict__ BTlo,
                     const float* __restrict__ bias,
                     const float* __restrict__ rowscale,
                     float* __restrict__ C, int M, int K) {
    constexpr int BM = 128, BK = 16, BKP = 24;
    constexpr int MI = BM / (WGM * 16);
    constexpr int NI = BN / (WGN * 8);
    constexpr int NBU2 = BN * 4 / 256;     // uint2 loads per thread per B matrix

    __shared__ __align__(16) __nv_bfloat16 sAhi[2][BM][BKP], sAlo[2][BM][BKP];
    __shared__ __align__(16) __nv_bfloat16 sBhi[2][BN][BKP], sBlo[2][BN][BKP];

    const int tid  = threadIdx.x;
    const int m0   = blockIdx.x * BM;
    const int w    = tid >> 5, lane = tid & 31;
    const int wm   = (w / WGN) * MI * 16;
    const int wn   = (w % WGN) * NI * 8;
    const int gid  = lane >> 2, tig = lane & 3;

    const int aRow  = lane & 15;
    const int aColB = (lane >> 4) * 16;
    const int bRow  = (lane & 7) + ((lane >> 4) << 3);
    const int bColB = ((lane >> 3) & 1) * 16;

    const uint32_t uAhi = (uint32_t)__cvta_generic_to_shared(&sAhi[0][0][0]);
    const uint32_t uAlo = (uint32_t)__cvta_generic_to_shared(&sAlo[0][0][0]);
    const uint32_t uBhi = (uint32_t)__cvta_generic_to_shared(&sBhi[0][0][0]);
    const uint32_t uBlo = (uint32_t)__cvta_generic_to_shared(&sBlo[0][0][0]);
    constexpr int ASTG = BM * BKP * 2;
    constexpr int BSTG = BN * BKP * 2;

    float4 rA[2];
    uint2  rBh[NBU2], rBl[NBU2];

    float acc[MI][NI][4];
#pragma unroll
    for (int i = 0; i < MI; i++)
#pragma unroll
        for (int j = 0; j < NI; j++) {
            acc[i][j][0] = 0.f; acc[i][j][1] = 0.f; acc[i][j][2] = 0.f; acc[i][j][3] = 0.f;
        }

    auto loadA = [&](int k0) {
#pragma unroll
        for (int u = 0; u < 2; u++) {
            int idx = tid + u * 256;
            int row = idx >> 2;
            int c4  = idx & 3;
            float4 v = make_float4(0.f, 0.f, 0.f, 0.f);
            int gm = m0 + row;
            if (gm < M) {
                v = *(const float4*)(A + (size_t)gm * K + k0 + c4 * 4);
                if (FUSE) {
                    int kk = k0 + c4 * 4;
                    v.x = fmaxf(v.x + bias[kk + 0], 0.f);
                    v.y = fmaxf(v.y + bias[kk + 1], 0.f);
                    v.z = fmaxf(v.z + bias[kk + 2], 0.f);
                    v.w = fmaxf(v.w + bias[kk + 3], 0.f);
                }
            }
            rA[u] = v;
        }
    };
    auto loadB = [&](int k0) {
#pragma unroll
        for (int u = 0; u < NBU2; u++) {
            int idx = tid + u * 256;       // over BN*4 uint2 slots (4 per row)
            int n = idx >> 2;
            int c = idx & 3;               // units of 4 bf16 = 8 bytes
            rBh[u] = *(const uint2*)(BThi + (size_t)n * K + k0 + c * 4);
            rBl[u] = *(const uint2*)(BTlo + (size_t)n * K + k0 + c * 4);
        }
    };
    auto storeTile = [&](int buf) {
#pragma unroll
        for (int u = 0; u < 2; u++) {
            int idx = tid + u * 256;
            int row = idx >> 2;
            int c4  = idx & 3;
            float4 v = rA[u];
            __nv_bfloat162 h0 = __floats2bfloat162_rn(v.x, v.y);
            __nv_bfloat162 h1 = __floats2bfloat162_rn(v.z, v.w);
            __nv_bfloat162 l0 = __floats2bfloat162_rn(v.x - __bfloat162float(h0.x),
                                                      v.y - __bfloat162float(h0.y));
            __nv_bfloat162 l1 = __floats2bfloat162_rn(v.z - __bfloat162float(h1.x),
                                                      v.w - __bfloat162float(h1.y));
            uint2 hw = make_uint2(*(uint32_t*)&h0, *(uint32_t*)&h1);
            uint2 lw = make_uint2(*(uint32_t*)&l0, *(uint32_t*)&l1);
            *(uint2*)&sAhi[buf][row][c4 * 4] = hw;
            *(uint2*)&sAlo[buf][row][c4 * 4] = lw;
        }
#pragma unroll
        for (int u = 0; u < NBU2; u++) {
            int idx = tid + u * 256;
            int n = idx >> 2;
            int c = idx & 3;
            *(uint2*)&sBhi[buf][n][c * 4] = rBh[u];
            *(uint2*)&sBlo[buf][n][c * 4] = rBl[u];
        }
    };

    const int nIter = K / BK;
    loadA(0); loadB(0);
    storeTile(0);
    __syncthreads();

    for (int it = 0; it < nIter; ++it) {
        if (it + 1 < nIter) { loadA((it + 1) * BK); loadB((it + 1) * BK); }
        const int p = it & 1;

        uint32_t ah[MI][4], al[MI][4];
        {
            uint32_t aBase = p * ASTG + (wm + aRow) * (BKP * 2) + aColB;
#pragma unroll
            for (int mi = 0; mi < MI; mi++) {
                ldsm_x4(ah[mi], uAhi + aBase + mi * 16 * (BKP * 2));
                ldsm_x4(al[mi], uAlo + aBase + mi * 16 * (BKP * 2));
            }
        }
        uint32_t bh[NI][2], bl[NI][2];
        {
            uint32_t bBase = p * BSTG + (wn + bRow) * (BKP * 2) + bColB;
#pragma unroll
            for (int q = 0; q < NI / 2; q++) {
                ldsm_x4(&bh[2 * q][0], uBhi + bBase + q * 16 * (BKP * 2));
                ldsm_x4(&bl[2 * q][0], uBlo + bBase + q * 16 * (BKP * 2));
            }
        }
#pragma unroll
        for (int mi = 0; mi < MI; mi++)
#pragma unroll
            for (int ni = 0; ni < NI; ni++) {
                MMA_BF16(acc[mi][ni], ah[mi], bh[ni]);
                MMA_BF16(acc[mi][ni], ah[mi], bl[ni]);
                MMA_BF16(acc[mi][ni], al[mi], bh[ni]);
            }

        if (it + 1 < nIter) storeTile((it + 1) & 1);
        __syncthreads();
    }

#pragma unroll
    for (int mi = 0; mi < MI; mi++) {
        int r0 = m0 + wm + mi * 16 + gid;
        int r1 = r0 + 8;
        float s0 = 1.f, s1 = 1.f;
        if (SCALE) {
            s0 = (r0 < M) ? rowscale[r0] : 0.f;
            s1 = (r1 < M) ? rowscale[r1] : 0.f;
        }
#pragma unroll
        for (int ni = 0; ni < NI; ni++) {
            int col = wn + ni * 8 + 2 * tig;
            if (r0 < M)
                *(float2*)(C + (size_t)r0 * BN + col) =
                    make_float2(acc[mi][ni][0] * s0, acc[mi][ni][1] * s0);
            if (r1 < M)
                *(float2*)(C + (size_t)r1 * BN + col) =
                    make_float2(acc[mi][ni][2] * s1, acc[mi][ni][3] * s1);
        }
    }
}

// ---------------- CSR gather aggregation ----------------
// h1 is RAW: agg[d] = dinv[d] * ( sum_s dinv[s]*h1[s] + dinv[d]*h1[d] )
__global__ void gather128_kernel(const float4* __restrict__ hs, const int* __restrict__ csrc,
                                 const int* __restrict__ rowptr, const float* __restrict__ dinv,
                                 float4* __restrict__ out) {
    int w = (blockIdx.x * blockDim.x + threadIdx.x) >> 5;
    if (w >= NN) return;
    int lane = threadIdx.x & 31;
    int begin = rowptr[w], end = rowptr[w + 1];
    float dv = __ldg(&dinv[w]);
    float4 self = __ldg(&hs[(size_t)w * 32 + lane]);
    float4 a0, a1, a2, a3;
    a0.x = dv * self.x; a0.y = dv * self.y; a0.z = dv * self.z; a0.w = dv * self.w;
    a1 = make_float4(0.f, 0.f, 0.f, 0.f);
    a2 = make_float4(0.f, 0.f, 0.f, 0.f);
    a3 = make_float4(0.f, 0.f, 0.f, 0.f);
    int j = begin;
    for (; j + 4 <= end; j += 4) {
        int s0 = __ldg(&csrc[j]);
        int s1 = __ldg(&csrc[j + 1]);
        int s2 = __ldg(&csrc[j + 2]);
        int s3 = __ldg(&csrc[j + 3]);
        float w0 = __ldg(&dinv[s0]);
        float w1 = __ldg(&dinv[s1]);
        float w2 = __ldg(&dinv[s2]);
        float w3 = __ldg(&dinv[s3]);
        float4 v0 = __ldg(&hs[(size_t)s0 * 32 + lane]);
        float4 v1 = __ldg(&hs[(size_t)s1 * 32 + lane]);
        float4 v2 = __ldg(&hs[(size_t)s2 * 32 + lane]);
        float4 v3 = __ldg(&hs[(size_t)s3 * 32 + lane]);
        a0.x = fmaf(w0, v0.x, a0.x); a0.y = fmaf(w0, v0.y, a0.y);
        a0.z = fmaf(w0, v0.z, a0.z); a0.w = fmaf(w0, v0.w, a0.w);
        a1.x = fmaf(w1, v1.x, a1.x); a1.y = fmaf(w1, v1.y, a1.y);
        a1.z = fmaf(w1, v1.z, a1.z); a1.w = fmaf(w1, v1.w, a1.w);
        a2.x = fmaf(w2, v2.x, a2.x); a2.y = fmaf(w2, v2.y, a2.y);
        a2.z = fmaf(w2, v2.z, a2.z); a2.w = fmaf(w2, v2.w, a2.w);
        a3.x = fmaf(w3, v3.x, a3.x); a3.y = fmaf(w3, v3.y, a3.y);
        a3.z = fmaf(w3, v3.z, a3.z); a3.w = fmaf(w3, v3.w, a3.w);
    }
    for (; j < end; ++j) {
        int s0 = __ldg(&csrc[j]);
        float w0 = __ldg(&dinv[s0]);
        float4 v0 = __ldg(&hs[(size_t)s0 * 32 + lane]);
        a0.x = fmaf(w0, v0.x, a0.x); a0.y = fmaf(w0, v0.y, a0.y);
        a0.z = fmaf(w0, v0.z, a0.z); a0.w = fmaf(w0, v0.w, a0.w);
    }
    float4 r;
    r.x = dv * ((a0.x + a1.x) + (a2.x + a3.x));
    r.y = dv * ((a0.y + a1.y) + (a2.y + a3.y));
    r.z = dv * ((a0.z + a1.z) + (a2.z + a3.z));
    r.w = dv * ((a0.w + a1.w) + (a2.w + a3.w));
    out[(size_t)w * 32 + lane] = r;
}

// h2 pre-scaled by dinv: out[d] = dinv[d]*(sum + h2[d]) + b2
__global__ void gather64_kernel(const float2* __restrict__ hs, const int* __restrict__ csrc,
                                const int* __restrict__ rowptr, const float* __restrict__ dinv,
                                const float* __restrict__ b2, float2* __restrict__ out) {
    int w = (blockIdx.x * blockDim.x + threadIdx.x) >> 5;
    if (w >= NN) return;
    int lane = threadIdx.x & 31;
    int begin = rowptr[w], end = rowptr[w + 1];
    float2 a0 = __ldg(&hs[(size_t)w * 32 + lane]);
    float2 a1 = make_float2(0.f, 0.f);
    float2 a2 = make_float2(0.f, 0.f);
    float2 a3 = make_float2(0.f, 0.f);
    int j = begin;
    for (; j + 4 <= end; j += 4) {
        int s0 = __ldg(&csrc[j]);
        int s1 = __ldg(&csrc[j + 1]);
        int s2 = __ldg(&csrc[j + 2]);
        int s3 = __ldg(&csrc[j + 3]);
        float2 v0 = __ldg(&hs[(size_t)s0 * 32 + lane]);
        float2 v1 = __ldg(&hs[(size_t)s1 * 32 + lane]);
        float2 v2 = __ldg(&hs[(size_t)s2 * 32 + lane]);
        float2 v3 = __ldg(&hs[(size_t)s3 * 32 + lane]);
        a0.x += v0.x; a0.y += v0.y;
        a1.x += v1.x; a1.y += v1.y;
        a2.x += v2.x; a2.y += v2.y;
        a3.x += v3.x; a3.y += v3.y;
    }
    for (; j < end; ++j) {
        int s0 = __ldg(&csrc[j]);
        float2 v0 = __ldg(&hs[(size_t)s0 * 32 + lane]);
        a0.x += v0.x; a0.y += v0.y;
    }
    float dv = dinv[w];
    float2 r;
    r.x = dv * ((a0.x + a1.x) + (a2.x + a3.x)) + b2[lane * 2 + 0];
    r.y = dv * ((a0.y + a1.y) + (a2.y + a3.y)) + b2[lane * 2 + 1];
    out[(size_t)w * 32 + lane] = r;
}

// ---------------- launch ----------------
extern "C" void kernel_launch(void* const* d_in, const int* in_sizes, int n_in,
                              void* d_out, int out_size) {
    const float* x   = (const float*)d_in[0];
    const int*   ei  = (const int*)d_in[1];   // int32 (JAX x64 disabled)
    const float* W1  = (const float*)d_in[2];
    const float* b1  = (const float*)d_in[3];
    const float* W2  = (const float*)d_in[4];
    const float* b2  = (const float*)d_in[5];
    float*       out = (float*)d_out;

    const int E = in_sizes[1] / 2;
    const int* src = ei;
    const int* dst = ei + E;

    void* p;
    cudaGetSymbolAddress(&p, g_h1);     float* h1     = (float*)p;
    cudaGetSymbolAddress(&p, g_agg1);   float* agg1   = (float*)p;
    cudaGetSymbolAddress(&p, g_h2);     float* h2     = (float*)p;
    cudaGetSymbolAddress(&p, g_dinv);   float* dinv   = (float*)p;
    cudaGetSymbolAddress(&p, g_deg);    int*   deg    = (int*)p;
    cudaGetSymbolAddress(&p, g_rowptr); int*   rowptr = (int*)p;
    cudaGetSymbolAddress(&p, g_fill);   int*   fill   = (int*)p;
    cudaGetSymbolAddress(&p, g_csrc);   int*   csrc   = (int*)p;
    cudaGetSymbolAddress(&p, g_bsum);   int*   bsum   = (int*)p;
    cudaGetSymbolAddress(&p, g_boff);   int*   boff   = (int*)p;
    cudaGetSymbolAddress(&p, g_w1hi);   __nv_bfloat16* w1hi = (__nv_bfloat16*)p;
    cudaGetSymbolAddress(&p, g_w1lo);   __nv_bfloat16* w1lo = (__nv_bfloat16*)p;
    cudaGetSymbolAddress(&p, g_w2hi);   __nv_bfloat16* w2hi = (__nv_bfloat16*)p;
    cudaGetSymbolAddress(&p, g_w2lo);   __nv_bfloat16* w2lo = (__nv_bfloat16*)p;

    static cudaStream_t s1 = nullptr;
    static cudaEvent_t  ePrep = nullptr, eGemm1 = nullptr;
    if (!s1) {
        cudaStreamCreateWithFlags(&s1, cudaStreamNonBlocking);
        cudaEventCreateWithFlags(&ePrep,  cudaEventDisableTiming);
        cudaEventCreateWithFlags(&eGemm1, cudaEventDisableTiming);
    }

    const int warpsGrid = (NN * 32 + 255) / 256;
    const int gemmGrid  = (NN + 127) / 128;

    // ---- main: prep (deg=0 + wsplit) ----
    prep_kernel<<<(NN + 255) / 256, 256>>>(deg, W1, W2, w1hi, w1lo, w2hi, w2lo);
    cudaEventRecord(ePrep, 0);

    // ---- s1: GEMM1 (raw, no dinv needed) starts immediately after prep ----
    cudaStreamWaitEvent(s1, ePrep, 0);
    mma_gemm_kernel<HID, 2, 4, false, false><<<gemmGrid, 256, 0, s1>>>(
        x, w1hi, w1lo, nullptr, nullptr, h1, NN, IND);
    cudaEventRecord(eGemm1, s1);

    // ---- main: full CSR chain overlaps GEMM1 ----
    deg_count_kernel<<<(E + 255) / 256, 256>>>(dst, deg, E);
    scan_reduce_kernel<<<SC_NB, SC_T>>>(deg, bsum, dinv, NN);
    scan_offsets_kernel<<<1, 128>>>(bsum, boff, rowptr, NN);
    scan_write_kernel<<<SC_NB, SC_T>>>(deg, boff, rowptr, fill, NN);
    fill_kernel<<<(E + 255) / 256, 256>>>(src, dst, fill, csrc, E);

    // ---- join, serial tail ----
    cudaStreamWaitEvent(0, eGemm1, 0);
    gather128_kernel<<<warpsGrid, 256>>>((const float4*)h1, csrc, rowptr, dinv, (float4*)agg1);
    mma_gemm_kernel<OUTD, 4, 2, true, true><<<gemmGrid, 256>>>(agg1, w2hi, w2lo, b1, dinv, h2, NN, HID);
    gather64_kernel<<<warpsGrid, 256>>>((const float2*)h2, csrc, rowptr, dinv, b2, (float2*)out);
}

// round 14
// speedup vs baseline: 1.8057x; 1.0529x over previous
#include <cuda_runtime.h>
#include <cuda_bf16.h>
#include <cuda_fp16.h>
#include <cstdint>

#define NN   50000
#define IND  256
#define HID  128
#define OUTD 64
#define EMAX 800000

// scan config
#define SC_T     256
#define SC_I     2
#define SC_CHUNK (SC_T * SC_I)
#define SC_NB    ((NN + SC_CHUNK - 1) / SC_CHUNK)

// -------- device scratch --------
__device__ __half g_h1[NN * HID];    // RAW x@W1, fp16
__device__ float  g_agg1[NN * HID];  // fp32 (GEMM2 input)
__device__ __half g_h2[NN * OUTD];   // dinv-scaled relu(agg1+b1)@W2, fp16
__device__ float  g_dinv[NN];
__device__ int    g_deg[NN];
__device__ int    g_rowptr[NN + 1];
__device__ int    g_fill[NN];
__device__ int    g_csrc[EMAX];
__device__ int    g_bsum[SC_NB];
__device__ int    g_boff[SC_NB];
__device__ __nv_bfloat16 g_w1hi[HID * IND];
__device__ __nv_bfloat16 g_w1lo[HID * IND];
__device__ __nv_bfloat16 g_w2hi[OUTD * HID];
__device__ __nv_bfloat16 g_w2lo[OUTD * HID];

// ---------------- prep: deg=0 + both weight splits ----------------
__global__ void prep_kernel(int* __restrict__ deg,
                            const float* __restrict__ W1, const float* __restrict__ W2,
                            __nv_bfloat16* __restrict__ T1h, __nv_bfloat16* __restrict__ T1l,
                            __nv_bfloat16* __restrict__ T2h, __nv_bfloat16* __restrict__ T2l) {
    int i = blockIdx.x * blockDim.x + threadIdx.x;
    if (i < NN) deg[i] = 0;
    const int n1 = IND * HID;
    const int n2 = HID * OUTD;
    if (i < n1) {
        int k = i / HID, n = i % HID;
        float v = W1[i];
        __nv_bfloat16 h = __float2bfloat16(v);
        T1h[(size_t)n * IND + k] = h;
        T1l[(size_t)n * IND + k] = __float2bfloat16(v - __bfloat162float(h));
    } else if (i < n1 + n2) {
        int j = i - n1;
        int k = j / OUTD, n = j % OUTD;
        float v = W2[j];
        __nv_bfloat16 h = __float2bfloat16(v);
        T2h[(size_t)n * HID + k] = h;
        T2l[(size_t)n * HID + k] = __float2bfloat16(v - __bfloat162float(h));
    }
}

__global__ void deg_count_kernel(const int* __restrict__ dst, int* __restrict__ deg, int E) {
    int i = blockIdx.x * blockDim.x + threadIdx.x;
    if (i < E) atomicAdd(&deg[dst[i]], 1);
}

// ---------------- scan chain ----------------
__global__ void scan_reduce_kernel(const int* __restrict__ deg, int* __restrict__ bsum,
                                   float* __restrict__ dinv, int n) {
    __shared__ int ws[SC_T / 32];
    int b = blockIdx.x, tid = threadIdx.x;
    int base = b * SC_CHUNK;
    int s = 0;
#pragma unroll
    for (int u = 0; u < SC_I; u++) {
        int i = base + u * SC_T + tid;
        if (i < n) {
            int c = deg[i];
            s += c;
            dinv[i] = rsqrtf((float)(c + 1));
        }
    }
#pragma unroll
    for (int d = 16; d; d >>= 1) s += __shfl_down_sync(0xffffffffu, s, d);
    if ((tid & 31) == 0) ws[tid >> 5] = s;
    __syncthreads();
    if (tid < 32) {
        int v = (tid < SC_T / 32) ? ws[tid] : 0;
#pragma unroll
        for (int d = 16; d; d >>= 1) v += __shfl_down_sync(0xffffffffu, v, d);
        if (tid == 0) bsum[b] = v;
    }
}

__global__ void scan_offsets_kernel(const int* __restrict__ bsum, int* __restrict__ boff,
                                    int* __restrict__ rowptr, int n) {
    __shared__ int ws[4];
    int tid = threadIdx.x;
    int lane = tid & 31, wid = tid >> 5;
    int v = (tid < SC_NB) ? bsum[tid] : 0;
    int x = v;
#pragma unroll
    for (int d = 1; d < 32; d <<= 1) {
        int y = __shfl_up_sync(0xffffffffu, x, d);
        if (lane >= d) x += y;
    }
    if (lane == 31) ws[wid] = x;
    __syncthreads();
    if (tid == 0) {
        int acc = 0;
#pragma unroll
        for (int k = 0; k < 4; k++) { int t = ws[k]; ws[k] = acc; acc += t; }
        rowptr[n] = acc;
    }
    __syncthreads();
    if (tid < SC_NB) boff[tid] = x - v + ws[wid];
}

__global__ void scan_write_kernel(const int* __restrict__ deg, const int* __restrict__ boff,
                                  int* __restrict__ rowptr, int* __restrict__ fill, int n) {
    __shared__ int sbuf[SC_CHUNK];
    __shared__ int ws[SC_T / 32];
    int b = blockIdx.x, tid = threadIdx.x;
    int lane = tid & 31, wid = tid >> 5;
    int base = b * SC_CHUNK;

#pragma unroll
    for (int u = 0; u < SC_I; u++) {
        int i = base + u * SC_T + tid;
        sbuf[u * SC_T + tid] = (i < n) ? deg[i] : 0;
    }
    __syncthreads();

    int v[SC_I];
    int tot = 0;
#pragma unroll
    for (int u = 0; u < SC_I; u++) {
        int d = sbuf[tid * SC_I + u];
        v[u] = tot;
        tot += d;
    }
    int x = tot;
#pragma unroll
    for (int d = 1; d < 32; d <<= 1) {
        int y = __shfl_up_sync(0xffffffffu, x, d);
        if (lane >= d) x += y;
    }
    if (lane == 31) ws[wid] = x;
    __syncthreads();
    if (wid == 0) {
        int y = (lane < SC_T / 32) ? ws[lane] : 0;
#pragma unroll
        for (int d = 1; d < 32; d <<= 1) {
            int z = __shfl_up_sync(0xffffffffu, y, d);
            if (lane >= d) y += z;
        }
        if (lane < SC_T / 32) ws[lane] = y;
    }
    __syncthreads();
    int off = boff[b] + (x - tot) + (wid ? ws[wid - 1] : 0);
#pragma unroll
    for (int u = 0; u < SC_I; u++) sbuf[tid * SC_I + u] = off + v[u];
    __syncthreads();

#pragma unroll
    for (int u = 0; u < SC_I; u++) {
        int i = base + u * SC_T + tid;
        if (i < n) {
            int r = sbuf[u * SC_T + tid];
            rowptr[i] = r;
            fill[i] = r;
        }
    }
}

__global__ void fill_kernel(const int* __restrict__ src, const int* __restrict__ dst,
                            int* __restrict__ fill, int* __restrict__ csrc, int E) {
    int i = blockIdx.x * blockDim.x + threadIdx.x;
    if (i >= E) return;
    int pos = atomicAdd(&fill[dst[i]], 1);
    csrc[pos] = src[i];
}

// ---------------- split-bf16 tensor-core GEMM with ldmatrix ----------------
#define MMA_BF16(c, a, b) asm volatile( \
    "mma.sync.aligned.m16n8k16.row.col.f32.bf16.bf16.f32 " \
    "{%0,%1,%2,%3}, {%4,%5,%6,%7}, {%8,%9}, {%0,%1,%2,%3};" \
    : "+f"((c)[0]), "+f"((c)[1]), "+f"((c)[2]), "+f"((c)[3]) \
    : "r"((a)[0]), "r"((a)[1]), "r"((a)[2]), "r"((a)[3]), "r"((b)[0]), "r"((b)[1]))

__device__ __forceinline__ void ldsm_x4(uint32_t* r, uint32_t addr) {
    asm volatile("ldmatrix.sync.aligned.m8n8.x4.shared.b16 {%0,%1,%2,%3}, [%4];"
                 : "=r"(r[0]), "=r"(r[1]), "=r"(r[2]), "=r"(r[3]) : "r"(addr));
}

// HOUT: write __half output; else float. SCALE: multiply row by rowscale.
template<int BN, int WGM, int WGN, bool FUSE, bool SCALE, bool HOUT>
__global__ __launch_bounds__(256, 2)
void mma_gemm_kernel(const float* __restrict__ A,
                     const __nv_bfloat16* __restrict__ BThi,
                     const __nv_bfloat16* __restrict__ BTlo,
                     const float* __restrict__ bias,
                     const float* __restrict__ rowscale,
                     void* __restrict__ Cout, int M, int K) {
    constexpr int BM = 128, BK = 16, BKP = 24;
    constexpr int MI = BM / (WGM * 16);
    constexpr int NI = BN / (WGN * 8);
    constexpr int NBU2 = BN * 4 / 256;

    __shared__ __align__(16) __nv_bfloat16 sAhi[2][BM][BKP], sAlo[2][BM][BKP];
    __shared__ __align__(16) __nv_bfloat16 sBhi[2][BN][BKP], sBlo[2][BN][BKP];

    const int tid  = threadIdx.x;
    const int m0   = blockIdx.x * BM;
    const int w    = tid >> 5, lane = tid & 31;
    const int wm   = (w / WGN) * MI * 16;
    const int wn   = (w % WGN) * NI * 8;
    const int gid  = lane >> 2, tig = lane & 3;

    const int aRow  = lane & 15;
    const int aColB = (lane >> 4) * 16;
    const int bRow  = (lane & 7) + ((lane >> 4) << 3);
    const int bColB = ((lane >> 3) & 1) * 16;

    const uint32_t uAhi = (uint32_t)__cvta_generic_to_shared(&sAhi[0][0][0]);
    const uint32_t uAlo = (uint32_t)__cvta_generic_to_shared(&sAlo[0][0][0]);
    const uint32_t uBhi = (uint32_t)__cvta_generic_to_shared(&sBhi[0][0][0]);
    const uint32_t uBlo = (uint32_t)__cvta_generic_to_shared(&sBlo[0][0][0]);
    constexpr int ASTG = BM * BKP * 2;
    constexpr int BSTG = BN * BKP * 2;

    float4 rA[2];
    uint2  rBh[NBU2], rBl[NBU2];

    float acc[MI][NI][4];
#pragma unroll
    for (int i = 0; i < MI; i++)
#pragma unroll
        for (int j = 0; j < NI; j++) {
            acc[i][j][0] = 0.f; acc[i][j][1] = 0.f; acc[i][j][2] = 0.f; acc[i][j][3] = 0.f;
        }

    auto loadA = [&](int k0) {
#pragma unroll
        for (int u = 0; u < 2; u++) {
            int idx = tid + u * 256;
            int row = idx >> 2;
            int c4  = idx & 3;
            float4 v = make_float4(0.f, 0.f, 0.f, 0.f);
            int gm = m0 + row;
            if (gm < M) {
                v = *(const float4*)(A + (size_t)gm * K + k0 + c4 * 4);
                if (FUSE) {
                    int kk = k0 + c4 * 4;
                    v.x = fmaxf(v.x + bias[kk + 0], 0.f);
                    v.y = fmaxf(v.y + bias[kk + 1], 0.f);
                    v.z = fmaxf(v.z + bias[kk + 2], 0.f);
                    v.w = fmaxf(v.w + bias[kk + 3], 0.f);
                }
            }
            rA[u] = v;
        }
    };
    auto loadB = [&](int k0) {
#pragma unroll
        for (int u = 0; u < NBU2; u++) {
            int idx = tid + u * 256;
            int n = idx >> 2;
            int c = idx & 3;
            rBh[u] = *(const uint2*)(BThi + (size_t)n * K + k0 + c * 4);
            rBl[u] = *(const uint2*)(BTlo + (size_t)n * K + k0 + c * 4);
        }
    };
    auto storeTile = [&](int buf) {
#pragma unroll
        for (int u = 0; u < 2; u++) {
            int idx = tid + u * 256;
            int row = idx >> 2;
            int c4  = idx & 3;
            float4 v = rA[u];
            __nv_bfloat162 h0 = __floats2bfloat162_rn(v.x, v.y);
            __nv_bfloat162 h1 = __floats2bfloat162_rn(v.z, v.w);
            __nv_bfloat162 l0 = __floats2bfloat162_rn(v.x - __bfloat162float(h0.x),
                                                      v.y - __bfloat162float(h0.y));
            __nv_bfloat162 l1 = __floats2bfloat162_rn(v.z - __bfloat162float(h1.x),
                                                      v.w - __bfloat162float(h1.y));
            uint2 hw = make_uint2(*(uint32_t*)&h0, *(uint32_t*)&h1);
            uint2 lw = make_uint2(*(uint32_t*)&l0, *(uint32_t*)&l1);
            *(uint2*)&sAhi[buf][row][c4 * 4] = hw;
            *(uint2*)&sAlo[buf][row][c4 * 4] = lw;
        }
#pragma unroll
        for (int u = 0; u < NBU2; u++) {
            int idx = tid + u * 256;
            int n = idx >> 2;
            int c = idx & 3;
            *(uint2*)&sBhi[buf][n][c * 4] = rBh[u];
            *(uint2*)&sBlo[buf][n][c * 4] = rBl[u];
        }
    };

    const int nIter = K / BK;
    loadA(0); loadB(0);
    storeTile(0);
    __syncthreads();

    for (int it = 0; it < nIter; ++it) {
        if (it + 1 < nIter) { loadA((it + 1) * BK); loadB((it + 1) * BK); }
        const int p = it & 1;

        uint32_t ah[MI][4], al[MI][4];
        {
            uint32_t aBase = p * ASTG + (wm + aRow) * (BKP * 2) + aColB;
#pragma unroll
            for (int mi = 0; mi < MI; mi++) {
                ldsm_x4(ah[mi], uAhi + aBase + mi * 16 * (BKP * 2));
                ldsm_x4(al[mi], uAlo + aBase + mi * 16 * (BKP * 2));
            }
        }
        uint32_t bh[NI][2], bl[NI][2];
        {
            uint32_t bBase = p * BSTG + (wn + bRow) * (BKP * 2) + bColB;
#pragma unroll
            for (int q = 0; q < NI / 2; q++) {
                ldsm_x4(&bh[2 * q][0], uBhi + bBase + q * 16 * (BKP * 2));
                ldsm_x4(&bl[2 * q][0], uBlo + bBase + q * 16 * (BKP * 2));
            }
        }
#pragma unroll
        for (int mi = 0; mi < MI; mi++)
#pragma unroll
            for (int ni = 0; ni < NI; ni++) {
                MMA_BF16(acc[mi][ni], ah[mi], bh[ni]);
                MMA_BF16(acc[mi][ni], ah[mi], bl[ni]);
                MMA_BF16(acc[mi][ni], al[mi], bh[ni]);
            }

        if (it + 1 < nIter) storeTile((it + 1) & 1);
        __syncthreads();
    }

#pragma unroll
    for (int mi = 0; mi < MI; mi++) {
        int r0 = m0 + wm + mi * 16 + gid;
        int r1 = r0 + 8;
        float s0 = 1.f, s1 = 1.f;
        if (SCALE) {
            s0 = (r0 < M) ? rowscale[r0] : 0.f;
            s1 = (r1 < M) ? rowscale[r1] : 0.f;
        }
#pragma unroll
        for (int ni = 0; ni < NI; ni++) {
            int col = wn + ni * 8 + 2 * tig;
            if (HOUT) {
                __half* C = (__half*)Cout;
                if (r0 < M)
                    *(__half2*)(C + (size_t)r0 * BN + col) =
                        __floats2half2_rn(acc[mi][ni][0] * s0, acc[mi][ni][1] * s0);
                if (r1 < M)
                    *(__half2*)(C + (size_t)r1 * BN + col) =
                        __floats2half2_rn(acc[mi][ni][2] * s1, acc[mi][ni][3] * s1);
            } else {
                float* C = (float*)Cout;
                if (r0 < M)
                    *(float2*)(C + (size_t)r0 * BN + col) =
                        make_float2(acc[mi][ni][0] * s0, acc[mi][ni][1] * s0);
                if (r1 < M)
                    *(float2*)(C + (size_t)r1 * BN + col) =
                        make_float2(acc[mi][ni][2] * s1, acc[mi][ni][3] * s1);
            }
        }
    }
}

// ---------------- CSR gather aggregation ----------------
// h1 RAW fp16 (row = 32 uint2 = 64 half2):
// agg[d] = dinv[d] * ( sum_s dinv[s]*h1[s] + dinv[d]*h1[d] )   (fp32 out)
__global__ void gather128_kernel(const uint2* __restrict__ hs, const int* __restrict__ csrc,
                                 const int* __restrict__ rowptr, const float* __restrict__ dinv,
                                 float4* __restrict__ out) {
    int w = (blockIdx.x * blockDim.x + threadIdx.x) >> 5;
    if (w >= NN) return;
    int lane = threadIdx.x & 31;
    int begin = rowptr[w], end = rowptr[w + 1];
    float dv = __ldg(&dinv[w]);
    uint2 sv = __ldg(&hs[(size_t)w * 32 + lane]);
    float2 sf0 = __half22float2(*(__half2*)&sv.x);
    float2 sf1 = __half22float2(*(__half2*)&sv.y);
    float4 a0, a1, a2, a3;
    a0.x = dv * sf0.x; a0.y = dv * sf0.y; a0.z = dv * sf1.x; a0.w = dv * sf1.y;
    a1 = make_float4(0.f, 0.f, 0.f, 0.f);
    a2 = make_float4(0.f, 0.f, 0.f, 0.f);
    a3 = make_float4(0.f, 0.f, 0.f, 0.f);
    int j = begin;
    for (; j + 4 <= end; j += 4) {
        int s0 = __ldg(&csrc[j]);
        int s1 = __ldg(&csrc[j + 1]);
        int s2 = __ldg(&csrc[j + 2]);
        int s3 = __ldg(&csrc[j + 3]);
        float w0 = __ldg(&dinv[s0]);
        float w1 = __ldg(&dinv[s1]);
        float w2 = __ldg(&dinv[s2]);
        float w3 = __ldg(&dinv[s3]);
        uint2 v0 = __ldg(&hs[(size_t)s0 * 32 + lane]);
        uint2 v1 = __ldg(&hs[(size_t)s1 * 32 + lane]);
        uint2 v2 = __ldg(&hs[(size_t)s2 * 32 + lane]);
        uint2 v3 = __ldg(&hs[(size_t)s3 * 32 + lane]);
        float2 f;
        f = __half22float2(*(__half2*)&v0.x); a0.x = fmaf(w0, f.x, a0.x); a0.y = fmaf(w0, f.y, a0.y);
        f = __half22float2(*(__half2*)&v0.y); a0.z = fmaf(w0, f.x, a0.z); a0.w = fmaf(w0, f.y, a0.w);
        f = __half22float2(*(__half2*)&v1.x); a1.x = fmaf(w1, f.x, a1.x); a1.y = fmaf(w1, f.y, a1.y);
        f = __half22float2(*(__half2*)&v1.y); a1.z = fmaf(w1, f.x, a1.z); a1.w = fmaf(w1, f.y, a1.w);
        f = __half22float2(*(__half2*)&v2.x); a2.x = fmaf(w2, f.x, a2.x); a2.y = fmaf(w2, f.y, a2.y);
        f = __half22float2(*(__half2*)&v2.y); a2.z = fmaf(w2, f.x, a2.z); a2.w = fmaf(w2, f.y, a2.w);
        f = __half22float2(*(__half2*)&v3.x); a3.x = fmaf(w3, f.x, a3.x); a3.y = fmaf(w3, f.y, a3.y);
        f = __half22float2(*(__half2*)&v3.y); a3.z = fmaf(w3, f.x, a3.z); a3.w = fmaf(w3, f.y, a3.w);
    }
    for (; j < end; ++j) {
        int s0 = __ldg(&csrc[j]);
        float w0 = __ldg(&dinv[s0]);
        uint2 v0 = __ldg(&hs[(size_t)s0 * 32 + lane]);
        float2 f;
        f = __half22float2(*(__half2*)&v0.x); a0.x = fmaf(w0, f.x, a0.x); a0.y = fmaf(w0, f.y, a0.y);
        f = __half22float2(*(__half2*)&v0.y); a0.z = fmaf(w0, f.x, a0.z); a0.w = fmaf(w0, f.y, a0.w);
    }
    float4 r;
    r.x = dv * ((a0.x + a1.x) + (a2.x + a3.x));
    r.y = dv * ((a0.y + a1.y) + (a2.y + a3.y));
    r.z = dv * ((a0.z + a1.z) + (a2.z + a3.z));
    r.w = dv * ((a0.w + a1.w) + (a2.w + a3.w));
    out[(size_t)w * 32 + lane] = r;
}

// h2 fp16 pre-scaled (row = 32 half2): out[d] = dinv[d]*(sum + h2[d]) + b2  (fp32 out)
__global__ void gather64_kernel(const uint32_t* __restrict__ hs, const int* __restrict__ csrc,
                                const int* __restrict__ rowptr, const float* __restrict__ dinv,
                                const float* __restrict__ b2, float2* __restrict__ out) {
    int w = (blockIdx.x * blockDim.x + threadIdx.x) >> 5;
    if (w >= NN) return;
    int lane = threadIdx.x & 31;
    int begin = rowptr[w], end = rowptr[w + 1];
    uint32_t sv = __ldg(&hs[(size_t)w * 32 + lane]);
    float2 sf = __half22float2(*(__half2*)&sv);
    float2 a0 = sf;
    float2 a1 = make_float2(0.f, 0.f);
    float2 a2 = make_float2(0.f, 0.f);
    float2 a3 = make_float2(0.f, 0.f);
    int j = begin;
    for (; j + 4 <= end; j += 4) {
        int s0 = __ldg(&csrc[j]);
        int s1 = __ldg(&csrc[j + 1]);
        int s2 = __ldg(&csrc[j + 2]);
        int s3 = __ldg(&csrc[j + 3]);
        uint32_t v0 = __ldg(&hs[(size_t)s0 * 32 + lane]);
        uint32_t v1 = __ldg(&hs[(size_t)s1 * 32 + lane]);
        uint32_t v2 = __ldg(&hs[(size_t)s2 * 32 + lane]);
        uint32_t v3 = __ldg(&hs[(size_t)s3 * 32 + lane]);
        float2 f;
        f = __half22float2(*(__half2*)&v0); a0.x += f.x; a0.y += f.y;
        f = __half22float2(*(__half2*)&v1); a1.x += f.x; a1.y += f.y;
        f = __half22float2(*(__half2*)&v2); a2.x += f.x; a2.y += f.y;
        f = __half22float2(*(__half2*)&v3); a3.x += f.x; a3.y += f.y;
    }
    for (; j < end; ++j) {
        int s0 = __ldg(&csrc[j]);
        uint32_t v0 = __ldg(&hs[(size_t)s0 * 32 + lane]);
        float2 f = __half22float2(*(__half2*)&v0);
        a0.x += f.x; a0.y += f.y;
    }
    float dv = dinv[w];
    float2 r;
    r.x = dv * ((a0.x + a1.x) + (a2.x + a3.x)) + b2[lane * 2 + 0];
    r.y = dv * ((a0.y + a1.y) + (a2.y + a3.y)) + b2[lane * 2 + 1];
    out[(size_t)w * 32 + lane] = r;
}

// ---------------- launch ----------------
extern "C" void kernel_launch(void* const* d_in, const int* in_sizes, int n_in,
                              void* d_out, int out_size) {
    const float* x   = (const float*)d_in[0];
    const int*   ei  = (const int*)d_in[1];   // int32 (JAX x64 disabled)
    const float* W1  = (const float*)d_in[2];
    const float* b1  = (const float*)d_in[3];
    const float* W2  = (const float*)d_in[4];
    const float* b2  = (const float*)d_in[5];
    float*       out = (float*)d_out;

    const int E = in_sizes[1] / 2;
    const int* src = ei;
    const int* dst = ei + E;

    void* p;
    cudaGetSymbolAddress(&p, g_h1);     __half* h1    = (__half*)p;
    cudaGetSymbolAddress(&p, g_agg1);   float* agg1   = (float*)p;
    cudaGetSymbolAddress(&p, g_h2);     __half* h2    = (__half*)p;
    cudaGetSymbolAddress(&p, g_dinv);   float* dinv   = (float*)p;
    cudaGetSymbolAddress(&p, g_deg);    int*   deg    = (int*)p;
    cudaGetSymbolAddress(&p, g_rowptr); int*   rowptr = (int*)p;
    cudaGetSymbolAddress(&p, g_fill);   int*   fill   = (int*)p;
    cudaGetSymbolAddress(&p, g_csrc);   int*   csrc   = (int*)p;
    cudaGetSymbolAddress(&p, g_bsum);   int*   bsum   = (int*)p;
    cudaGetSymbolAddress(&p, g_boff);   int*   boff   = (int*)p;
    cudaGetSymbolAddress(&p, g_w1hi);   __nv_bfloat16* w1hi = (__nv_bfloat16*)p;
    cudaGetSymbolAddress(&p, g_w1lo);   __nv_bfloat16* w1lo = (__nv_bfloat16*)p;
    cudaGetSymbolAddress(&p, g_w2hi);   __nv_bfloat16* w2hi = (__nv_bfloat16*)p;
    cudaGetSymbolAddress(&p, g_w2lo);   __nv_bfloat16* w2lo = (__nv_bfloat16*)p;

    static cudaStream_t s1 = nullptr;
    static cudaEvent_t  ePrep = nullptr, eGemm1 = nullptr;
    if (!s1) {
        cudaStreamCreateWithFlags(&s1, cudaStreamNonBlocking);
        cudaEventCreateWithFlags(&ePrep,  cudaEventDisableTiming);
        cudaEventCreateWithFlags(&eGemm1, cudaEventDisableTiming);
    }

    const int warpsGrid = (NN * 32 + 255) / 256;
    const int gemmGrid  = (NN + 127) / 128;

    // ---- main: prep (deg=0 + wsplit) ----
    prep_kernel<<<(NN + 255) / 256, 256>>>(deg, W1, W2, w1hi, w1lo, w2hi, w2lo);
    cudaEventRecord(ePrep, 0);

    // ---- s1: GEMM1 (raw fp16 out) starts right after prep ----
    cudaStreamWaitEvent(s1, ePrep, 0);
    mma_gemm_kernel<HID, 2, 4, false, false, true><<<gemmGrid, 256, 0, s1>>>(
        x, w1hi, w1lo, nullptr, nullptr, h1, NN, IND);
    cudaEventRecord(eGemm1, s1);

    // ---- main: CSR chain overlaps GEMM1 ----
    deg_count_kernel<<<(E + 255) / 256, 256>>>(dst, deg, E);
    scan_reduce_kernel<<<SC_NB, SC_T>>>(deg, bsum, dinv, NN);
    scan_offsets_kernel<<<1, 128>>>(bsum, boff, rowptr, NN);
    scan_write_kernel<<<SC_NB, SC_T>>>(deg, boff, rowptr, fill, NN);
    fill_kernel<<<(E + 255) / 256, 256>>>(src, dst, fill, csrc, E);

    // ---- join, serial tail ----
    cudaStreamWaitEvent(0, eGemm1, 0);
    gather128_kernel<<<warpsGrid, 256>>>((const uint2*)h1, csrc, rowptr, dinv, (float4*)agg1);
    mma_gemm_kernel<OUTD, 4, 2, true, true, true><<<gemmGrid, 256>>>(
        agg1, w2hi, w2lo, b1, dinv, h2, NN, HID);
    gather64_kernel<<<warpsGrid, 256>>>((const uint32_t*)h2, csrc, rowptr, dinv, b2, (float2*)out);
}

// round 15
// speedup vs baseline: 2.0346x; 1.1268x over previous
#include <cuda_runtime.h>
#include <cuda_fp16.h>
#include <cstdint>

#define NN   50000
#define IND  256
#define HID  128
#define OUTD 64
#define EMAX 800000

// scan config
#define SC_T     256
#define SC_I     2
#define SC_CHUNK (SC_T * SC_I)
#define SC_NB    ((NN + SC_CHUNK - 1) / SC_CHUNK)

// -------- device scratch --------
__device__ __half g_h1[NN * HID];    // RAW x@W1, fp16
__device__ float  g_agg1[NN * HID];  // fp32 (GEMM2 input)
__device__ __half g_h2[NN * OUTD];   // dinv-scaled relu(agg1+b1)@W2, fp16
__device__ float  g_dinv[NN];
__device__ int    g_deg[NN];
__device__ int    g_rowptr[NN + 1];
__device__ int    g_fill[NN];
__device__ int    g_csrc[EMAX];
__device__ int    g_bsum[SC_NB];
__device__ int    g_boff[SC_NB];
__device__ __half g_w1t[HID * IND];  // W1^T fp16
__device__ __half g_w2t[OUTD * HID]; // W2^T fp16

// ---------------- prep: deg=0 + both weight transposes (fp16) ----------------
__global__ void prep_kernel(int* __restrict__ deg,
                            const float* __restrict__ W1, const float* __restrict__ W2,
                            __half* __restrict__ T1, __half* __restrict__ T2) {
    int i = blockIdx.x * blockDim.x + threadIdx.x;
    if (i < NN) deg[i] = 0;
    const int n1 = IND * HID;
    const int n2 = HID * OUTD;
    if (i < n1) {
        int k = i / HID, n = i % HID;
        T1[(size_t)n * IND + k] = __float2half(W1[i]);
    } else if (i < n1 + n2) {
        int j = i - n1;
        int k = j / OUTD, n = j % OUTD;
        T2[(size_t)n * HID + k] = __float2half(W2[j]);
    }
}

__global__ void deg_count_kernel(const int* __restrict__ dst, int* __restrict__ deg, int E) {
    int i = blockIdx.x * blockDim.x + threadIdx.x;
    if (i < E) atomicAdd(&deg[dst[i]], 1);
}

// ---------------- scan chain ----------------
__global__ void scan_reduce_kernel(const int* __restrict__ deg, int* __restrict__ bsum,
                                   float* __restrict__ dinv, int n) {
    __shared__ int ws[SC_T / 32];
    int b = blockIdx.x, tid = threadIdx.x;
    int base = b * SC_CHUNK;
    int s = 0;
#pragma unroll
    for (int u = 0; u < SC_I; u++) {
        int i = base + u * SC_T + tid;
        if (i < n) {
            int c = deg[i];
            s += c;
            dinv[i] = rsqrtf((float)(c + 1));
        }
    }
#pragma unroll
    for (int d = 16; d; d >>= 1) s += __shfl_down_sync(0xffffffffu, s, d);
    if ((tid & 31) == 0) ws[tid >> 5] = s;
    __syncthreads();
    if (tid < 32) {
        int v = (tid < SC_T / 32) ? ws[tid] : 0;
#pragma unroll
        for (int d = 16; d; d >>= 1) v += __shfl_down_sync(0xffffffffu, v, d);
        if (tid == 0) bsum[b] = v;
    }
}

__global__ void scan_offsets_kernel(const int* __restrict__ bsum, int* __restrict__ boff,
                                    int* __restrict__ rowptr, int n) {
    __shared__ int ws[4];
    int tid = threadIdx.x;
    int lane = tid & 31, wid = tid >> 5;
    int v = (tid < SC_NB) ? bsum[tid] : 0;
    int x = v;
#pragma unroll
    for (int d = 1; d < 32; d <<= 1) {
        int y = __shfl_up_sync(0xffffffffu, x, d);
        if (lane >= d) x += y;
    }
    if (lane == 31) ws[wid] = x;
    __syncthreads();
    if (tid == 0) {
        int acc = 0;
#pragma unroll
        for (int k = 0; k < 4; k++) { int t = ws[k]; ws[k] = acc; acc += t; }
        rowptr[n] = acc;
    }
    __syncthreads();
    if (tid < SC_NB) boff[tid] = x - v + ws[wid];
}

__global__ void scan_write_kernel(const int* __restrict__ deg, const int* __restrict__ boff,
                                  int* __restrict__ rowptr, int* __restrict__ fill, int n) {
    __shared__ int sbuf[SC_CHUNK];
    __shared__ int ws[SC_T / 32];
    int b = blockIdx.x, tid = threadIdx.x;
    int lane = tid & 31, wid = tid >> 5;
    int base = b * SC_CHUNK;

#pragma unroll
    for (int u = 0; u < SC_I; u++) {
        int i = base + u * SC_T + tid;
        sbuf[u * SC_T + tid] = (i < n) ? deg[i] : 0;
    }
    __syncthreads();

    int v[SC_I];
    int tot = 0;
#pragma unroll
    for (int u = 0; u < SC_I; u++) {
        int d = sbuf[tid * SC_I + u];
        v[u] = tot;
        tot += d;
    }
    int x = tot;
#pragma unroll
    for (int d = 1; d < 32; d <<= 1) {
        int y = __shfl_up_sync(0xffffffffu, x, d);
        if (lane >= d) x += y;
    }
    if (lane == 31) ws[wid] = x;
    __syncthreads();
    if (wid == 0) {
        int y = (lane < SC_T / 32) ? ws[lane] : 0;
#pragma unroll
        for (int d = 1; d < 32; d <<= 1) {
            int z = __shfl_up_sync(0xffffffffu, y, d);
            if (lane >= d) y += z;
        }
        if (lane < SC_T / 32) ws[lane] = y;
    }
    __syncthreads();
    int off = boff[b] + (x - tot) + (wid ? ws[wid - 1] : 0);
#pragma unroll
    for (int u = 0; u < SC_I; u++) sbuf[tid * SC_I + u] = off + v[u];
    __syncthreads();

#pragma unroll
    for (int u = 0; u < SC_I; u++) {
        int i = base + u * SC_T + tid;
        if (i < n) {
            int r = sbuf[u * SC_T + tid];
            rowptr[i] = r;
            fill[i] = r;
        }
    }
}

__global__ void fill_kernel(const int* __restrict__ src, const int* __restrict__ dst,
                            int* __restrict__ fill, int* __restrict__ csrc, int E) {
    int i = blockIdx.x * blockDim.x + threadIdx.x;
    if (i >= E) return;
    int pos = atomicAdd(&fill[dst[i]], 1);
    csrc[pos] = src[i];
}

// ---------------- fp16 tensor-core GEMM with ldmatrix ----------------
#define MMA_F16(c, a, b) asm volatile( \
    "mma.sync.aligned.m16n8k16.row.col.f32.f16.f16.f32 " \
    "{%0,%1,%2,%3}, {%4,%5,%6,%7}, {%8,%9}, {%0,%1,%2,%3};" \
    : "+f"((c)[0]), "+f"((c)[1]), "+f"((c)[2]), "+f"((c)[3]) \
    : "r"((a)[0]), "r"((a)[1]), "r"((a)[2]), "r"((a)[3]), "r"((b)[0]), "r"((b)[1]))

__device__ __forceinline__ void ldsm_x4(uint32_t* r, uint32_t addr) {
    asm volatile("ldmatrix.sync.aligned.m8n8.x4.shared.b16 {%0,%1,%2,%3}, [%4];"
                 : "=r"(r[0]), "=r"(r[1]), "=r"(r[2]), "=r"(r[3]) : "r"(addr));
}

// HOUT: write __half output; else float. SCALE: multiply row by rowscale.
template<int BN, int WGM, int WGN, bool FUSE, bool SCALE, bool HOUT>
__global__ __launch_bounds__(256, 2)
void mma_gemm_kernel(const float* __restrict__ A,
                     const __half* __restrict__ BT,
                     const float* __restrict__ bias,
                     const float* __restrict__ rowscale,
                     void* __restrict__ Cout, int M, int K) {
    constexpr int BM = 128, BK = 16, BKP = 24;
    constexpr int MI = BM / (WGM * 16);
    constexpr int NI = BN / (WGN * 8);
    constexpr int NBU2 = BN * 4 / 256;

    __shared__ __align__(16) __half sA[2][BM][BKP];
    __shared__ __align__(16) __half sB[2][BN][BKP];

    const int tid  = threadIdx.x;
    const int m0   = blockIdx.x * BM;
    const int w    = tid >> 5, lane = tid & 31;
    const int wm   = (w / WGN) * MI * 16;
    const int wn   = (w % WGN) * NI * 8;
    const int gid  = lane >> 2, tig = lane & 3;

    const int aRow  = lane & 15;
    const int aColB = (lane >> 4) * 16;
    const int bRow  = (lane & 7) + ((lane >> 4) << 3);
    const int bColB = ((lane >> 3) & 1) * 16;

    const uint32_t uA = (uint32_t)__cvta_generic_to_shared(&sA[0][0][0]);
    const uint32_t uB = (uint32_t)__cvta_generic_to_shared(&sB[0][0][0]);
    constexpr int ASTG = BM * BKP * 2;
    constexpr int BSTG = BN * BKP * 2;

    float4 rA[2];
    uint2  rB[NBU2];

    float acc[MI][NI][4];
#pragma unroll
    for (int i = 0; i < MI; i++)
#pragma unroll
        for (int j = 0; j < NI; j++) {
            acc[i][j][0] = 0.f; acc[i][j][1] = 0.f; acc[i][j][2] = 0.f; acc[i][j][3] = 0.f;
        }

    auto loadA = [&](int k0) {
#pragma unroll
        for (int u = 0; u < 2; u++) {
            int idx = tid + u * 256;
            int row = idx >> 2;
            int c4  = idx & 3;
            float4 v = make_float4(0.f, 0.f, 0.f, 0.f);
            int gm = m0 + row;
            if (gm < M) {
                v = *(const float4*)(A + (size_t)gm * K + k0 + c4 * 4);
                if (FUSE) {
                    int kk = k0 + c4 * 4;
                    v.x = fmaxf(v.x + bias[kk + 0], 0.f);
                    v.y = fmaxf(v.y + bias[kk + 1], 0.f);
                    v.z = fmaxf(v.z + bias[kk + 2], 0.f);
                    v.w = fmaxf(v.w + bias[kk + 3], 0.f);
                }
            }
            rA[u] = v;
        }
    };
    auto loadB = [&](int k0) {
#pragma unroll
        for (int u = 0; u < NBU2; u++) {
            int idx = tid + u * 256;
            int n = idx >> 2;
            int c = idx & 3;
            rB[u] = *(const uint2*)(BT + (size_t)n * K + k0 + c * 4);
        }
    };
    auto storeTile = [&](int buf) {
#pragma unroll
        for (int u = 0; u < 2; u++) {
            int idx = tid + u * 256;
            int row = idx >> 2;
            int c4  = idx & 3;
            float4 v = rA[u];
            __half2 h0 = __floats2half2_rn(v.x, v.y);
            __half2 h1 = __floats2half2_rn(v.z, v.w);
            *(uint2*)&sA[buf][row][c4 * 4] = make_uint2(*(uint32_t*)&h0, *(uint32_t*)&h1);
        }
#pragma unroll
        for (int u = 0; u < NBU2; u++) {
            int idx = tid + u * 256;
            int n = idx >> 2;
            int c = idx & 3;
            *(uint2*)&sB[buf][n][c * 4] = rB[u];
        }
    };

    const int nIter = K / BK;
    loadA(0); loadB(0);
    storeTile(0);
    __syncthreads();

    for (int it = 0; it < nIter; ++it) {
        if (it + 1 < nIter) { loadA((it + 1) * BK); loadB((it + 1) * BK); }
        const int p = it & 1;

        uint32_t af[MI][4];
        {
            uint32_t aBase = p * ASTG + (wm + aRow) * (BKP * 2) + aColB;
#pragma unroll
            for (int mi = 0; mi < MI; mi++)
                ldsm_x4(af[mi], uA + aBase + mi * 16 * (BKP * 2));
        }
        uint32_t bf[NI][2];
        {
            uint32_t bBase = p * BSTG + (wn + bRow) * (BKP * 2) + bColB;
#pragma unroll
            for (int q = 0; q < NI / 2; q++)
                ldsm_x4(&bf[2 * q][0], uB + bBase + q * 16 * (BKP * 2));
        }
#pragma unroll
        for (int mi = 0; mi < MI; mi++)
#pragma unroll
            for (int ni = 0; ni < NI; ni++)
                MMA_F16(acc[mi][ni], af[mi], bf[ni]);

        if (it + 1 < nIter) storeTile((it + 1) & 1);
        __syncthreads();
    }

#pragma unroll
    for (int mi = 0; mi < MI; mi++) {
        int r0 = m0 + wm + mi * 16 + gid;
        int r1 = r0 + 8;
        float s0 = 1.f, s1 = 1.f;
        if (SCALE) {
            s0 = (r0 < M) ? rowscale[r0] : 0.f;
            s1 = (r1 < M) ? rowscale[r1] : 0.f;
        }
#pragma unroll
        for (int ni = 0; ni < NI; ni++) {
            int col = wn + ni * 8 + 2 * tig;
            if (HOUT) {
                __half* C = (__half*)Cout;
                if (r0 < M)
                    *(__half2*)(C + (size_t)r0 * BN + col) =
                        __floats2half2_rn(acc[mi][ni][0] * s0, acc[mi][ni][1] * s0);
                if (r1 < M)
                    *(__half2*)(C + (size_t)r1 * BN + col) =
                        __floats2half2_rn(acc[mi][ni][2] * s1, acc[mi][ni][3] * s1);
            } else {
                float* C = (float*)Cout;
                if (r0 < M)
                    *(float2*)(C + (size_t)r0 * BN + col) =
                        make_float2(acc[mi][ni][0] * s0, acc[mi][ni][1] * s0);
                if (r1 < M)
                    *(float2*)(C + (size_t)r1 * BN + col) =
                        make_float2(acc[mi][ni][2] * s1, acc[mi][ni][3] * s1);
            }
        }
    }
}

// ---------------- CSR gather aggregation ----------------
// h1 RAW fp16 (row = 32 uint2):
// agg[d] = dinv[d] * ( sum_s dinv[s]*h1[s] + dinv[d]*h1[d] )   (fp32 out)
__global__ void gather128_kernel(const uint2* __restrict__ hs, const int* __restrict__ csrc,
                                 const int* __restrict__ rowptr, const float* __restrict__ dinv,
                                 float4* __restrict__ out) {
    int w = (blockIdx.x * blockDim.x + threadIdx.x) >> 5;
    if (w >= NN) return;
    int lane = threadIdx.x & 31;
    int begin = rowptr[w], end = rowptr[w + 1];
    float dv = __ldg(&dinv[w]);
    uint2 sv = __ldg(&hs[(size_t)w * 32 + lane]);
    float2 sf0 = __half22float2(*(__half2*)&sv.x);
    float2 sf1 = __half22float2(*(__half2*)&sv.y);
    float4 a0, a1, a2, a3;
    a0.x = dv * sf0.x; a0.y = dv * sf0.y; a0.z = dv * sf1.x; a0.w = dv * sf1.y;
    a1 = make_float4(0.f, 0.f, 0.f, 0.f);
    a2 = make_float4(0.f, 0.f, 0.f, 0.f);
    a3 = make_float4(0.f, 0.f, 0.f, 0.f);
    int j = begin;
    for (; j + 4 <= end; j += 4) {
        int s0 = __ldg(&csrc[j]);
        int s1 = __ldg(&csrc[j + 1]);
        int s2 = __ldg(&csrc[j + 2]);
        int s3 = __ldg(&csrc[j + 3]);
        float w0 = __ldg(&dinv[s0]);
        float w1 = __ldg(&dinv[s1]);
        float w2 = __ldg(&dinv[s2]);
        float w3 = __ldg(&dinv[s3]);
        uint2 v0 = __ldg(&hs[(size_t)s0 * 32 + lane]);
        uint2 v1 = __ldg(&hs[(size_t)s1 * 32 + lane]);
        uint2 v2 = __ldg(&hs[(size_t)s2 * 32 + lane]);
        uint2 v3 = __ldg(&hs[(size_t)s3 * 32 + lane]);
        float2 f;
        f = __half22float2(*(__half2*)&v0.x); a0.x = fmaf(w0, f.x, a0.x); a0.y = fmaf(w0, f.y, a0.y);
        f = __half22float2(*(__half2*)&v0.y); a0.z = fmaf(w0, f.x, a0.z); a0.w = fmaf(w0, f.y, a0.w);
        f = __half22float2(*(__half2*)&v1.x); a1.x = fmaf(w1, f.x, a1.x); a1.y = fmaf(w1, f.y, a1.y);
        f = __half22float2(*(__half2*)&v1.y); a1.z = fmaf(w1, f.x, a1.z); a1.w = fmaf(w1, f.y, a1.w);
        f = __half22float2(*(__half2*)&v2.x); a2.x = fmaf(w2, f.x, a2.x); a2.y = fmaf(w2, f.y, a2.y);
        f = __half22float2(*(__half2*)&v2.y); a2.z = fmaf(w2, f.x, a2.z); a2.w = fmaf(w2, f.y, a2.w);
        f = __half22float2(*(__half2*)&v3.x); a3.x = fmaf(w3, f.x, a3.x); a3.y = fmaf(w3, f.y, a3.y);
        f = __half22float2(*(__half2*)&v3.y); a3.z = fmaf(w3, f.x, a3.z); a3.w = fmaf(w3, f.y, a3.w);
    }
    for (; j < end; ++j) {
        int s0 = __ldg(&csrc[j]);
        float w0 = __ldg(&dinv[s0]);
        uint2 v0 = __ldg(&hs[(size_t)s0 * 32 + lane]);
        float2 f;
        f = __half22float2(*(__half2*)&v0.x); a0.x = fmaf(w0, f.x, a0.x); a0.y = fmaf(w0, f.y, a0.y);
        f = __half22float2(*(__half2*)&v0.y); a0.z = fmaf(w0, f.x, a0.z); a0.w = fmaf(w0, f.y, a0.w);
    }
    float4 r;
    r.x = dv * ((a0.x + a1.x) + (a2.x + a3.x));
    r.y = dv * ((a0.y + a1.y) + (a2.y + a3.y));
    r.z = dv * ((a0.z + a1.z) + (a2.z + a3.z));
    r.w = dv * ((a0.w + a1.w) + (a2.w + a3.w));
    out[(size_t)w * 32 + lane] = r;
}

// h2 fp16 pre-scaled (row = 32 half2): out[d] = dinv[d]*(sum + h2[d]) + b2  (fp32 out)
__global__ void gather64_kernel(const uint32_t* __restrict__ hs, const int* __restrict__ csrc,
                                const int* __restrict__ rowptr, const float* __restrict__ dinv,
                                const float* __restrict__ b2, float2* __restrict__ out) {
    int w = (blockIdx.x * blockDim.x + threadIdx.x) >> 5;
    if (w >= NN) return;
    int lane = threadIdx.x & 31;
    int begin = rowptr[w], end = rowptr[w + 1];
    uint32_t sv = __ldg(&hs[(size_t)w * 32 + lane]);
    float2 a0 = __half22float2(*(__half2*)&sv);
    float2 a1 = make_float2(0.f, 0.f);
    float2 a2 = make_float2(0.f, 0.f);
    float2 a3 = make_float2(0.f, 0.f);
    int j = begin;
    for (; j + 4 <= end; j += 4) {
        int s0 = __ldg(&csrc[j]);
        int s1 = __ldg(&csrc[j + 1]);
        int s2 = __ldg(&csrc[j + 2]);
        int s3 = __ldg(&csrc[j + 3]);
        uint32_t v0 = __ldg(&hs[(size_t)s0 * 32 + lane]);
        uint32_t v1 = __ldg(&hs[(size_t)s1 * 32 + lane]);
        uint32_t v2 = __ldg(&hs[(size_t)s2 * 32 + lane]);
        uint32_t v3 = __ldg(&hs[(size_t)s3 * 32 + lane]);
        float2 f;
        f = __half22float2(*(__half2*)&v0); a0.x += f.x; a0.y += f.y;
        f = __half22float2(*(__half2*)&v1); a1.x += f.x; a1.y += f.y;
        f = __half22float2(*(__half2*)&v2); a2.x += f.x; a2.y += f.y;
        f = __half22float2(*(__half2*)&v3); a3.x += f.x; a3.y += f.y;
    }
    for (; j < end; ++j) {
        int s0 = __ldg(&csrc[j]);
        uint32_t v0 = __ldg(&hs[(size_t)s0 * 32 + lane]);
        float2 f = __half22float2(*(__half2*)&v0);
        a0.x += f.x; a0.y += f.y;
    }
    float dv = dinv[w];
    float2 r;
    r.x = dv * ((a0.x + a1.x) + (a2.x + a3.x)) + b2[lane * 2 + 0];
    r.y = dv * ((a0.y + a1.y) + (a2.y + a3.y)) + b2[lane * 2 + 1];
    out[(size_t)w * 32 + lane] = r;
}

// ---------------- launch ----------------
extern "C" void kernel_launch(void* const* d_in, const int* in_sizes, int n_in,
                              void* d_out, int out_size) {
    const float* x   = (const float*)d_in[0];
    const int*   ei  = (const int*)d_in[1];   // int32 (JAX x64 disabled)
    const float* W1  = (const float*)d_in[2];
    const float* b1  = (const float*)d_in[3];
    const float* W2  = (const float*)d_in[4];
    const float* b2  = (const float*)d_in[5];
    float*       out = (float*)d_out;

    const int E = in_sizes[1] / 2;
    const int* src = ei;
    const int* dst = ei + E;

    void* p;
    cudaGetSymbolAddress(&p, g_h1);     __half* h1    = (__half*)p;
    cudaGetSymbolAddress(&p, g_agg1);   float* agg1   = (float*)p;
    cudaGetSymbolAddress(&p, g_h2);     __half* h2    = (__half*)p;
    cudaGetSymbolAddress(&p, g_dinv);   float* dinv   = (float*)p;
    cudaGetSymbolAddress(&p, g_deg);    int*   deg    = (int*)p;
    cudaGetSymbolAddress(&p, g_rowptr); int*   rowptr = (int*)p;
    cudaGetSymbolAddress(&p, g_fill);   int*   fill   = (int*)p;
    cudaGetSymbolAddress(&p, g_csrc);   int*   csrc   = (int*)p;
    cudaGetSymbolAddress(&p, g_bsum);   int*   bsum   = (int*)p;
    cudaGetSymbolAddress(&p, g_boff);   int*   boff   = (int*)p;
    cudaGetSymbolAddress(&p, g_w1t);    __half* w1t   = (__half*)p;
    cudaGetSymbolAddress(&p, g_w2t);    __half* w2t   = (__half*)p;

    static cudaStream_t s1 = nullptr;
    static cudaEvent_t  ePrep = nullptr, eGemm1 = nullptr;
    if (!s1) {
        cudaStreamCreateWithFlags(&s1, cudaStreamNonBlocking);
        cudaEventCreateWithFlags(&ePrep,  cudaEventDisableTiming);
        cudaEventCreateWithFlags(&eGemm1, cudaEventDisableTiming);
    }

    const int warpsGrid = (NN * 32 + 255) / 256;
    const int gemmGrid  = (NN + 127) / 128;

    // ---- main: prep (deg=0 + weight transposes) ----
    prep_kernel<<<(NN + 255) / 256, 256>>>(deg, W1, W2, w1t, w2t);
    cudaEventRecord(ePrep, 0);

    // ---- s1: GEMM1 (raw fp16 out) starts right after prep ----
    cudaStreamWaitEvent(s1, ePrep, 0);
    mma_gemm_kernel<HID, 2, 4, false, false, true><<<gemmGrid, 256, 0, s1>>>(
        x, w1t, nullptr, nullptr, h1, NN, IND);
    cudaEventRecord(eGemm1, s1);

    // ---- main: CSR chain overlaps GEMM1 ----
    deg_count_kernel<<<(E + 255) / 256, 256>>>(dst, deg, E);
    scan_reduce_kernel<<<SC_NB, SC_T>>>(deg, bsum, dinv, NN);
    scan_offsets_kernel<<<1, 128>>>(bsum, boff, rowptr, NN);
    scan_write_kernel<<<SC_NB, SC_T>>>(deg, boff, rowptr, fill, NN);
    fill_kernel<<<(E + 255) / 256, 256>>>(src, dst, fill, csrc, E);

    // ---- join, serial tail ----
    cudaStreamWaitEvent(0, eGemm1, 0);
    gather128_kernel<<<warpsGrid, 256>>>((const uint2*)h1, csrc, rowptr, dinv, (float4*)agg1);
    mma_gemm_kernel<OUTD, 4, 2, true, true, true><<<gemmGrid, 256>>>(
        agg1, w2t, b1, dinv, h2, NN, HID);
    gather64_kernel<<<warpsGrid, 256>>>((const uint32_t*)h2, csrc, rowptr, dinv, b2, (float2*)out);
}